// round 11
// baseline (speedup 1.0000x reference)
#include <cuda_runtime.h>
#include <cuda_bf16.h>
#include <cuda_fp16.h>
#include <math.h>
#include <stdint.h>

#define NB 4
#define NH 16
#define TT 2048
#define DH 64
#define CC 1024
#define MROWS (NB*TT)   // 8192
#define KDIM  1024

// ---------------------------------------------------------------------------
// Scratch (__device__ globals; allocation-free rule)
// ---------------------------------------------------------------------------
__device__ float g_y[MROWS*CC];      // [B,T,C] fp32 attention output

// split q/k in bf16, v in fp16 (PV runs fp16), all [B,H,T,D] hi+lo planes
__device__ __nv_bfloat16 g_qh[NB*NH*TT*DH];
__device__ __nv_bfloat16 g_ql[NB*NH*TT*DH];
__device__ __nv_bfloat16 g_kh[NB*NH*TT*DH];
__device__ __nv_bfloat16 g_kl[NB*NH*TT*DH];
__device__ __half        g_vh[NB*NH*TT*DH];
__device__ __half        g_vl[NB*NH*TT*DH];

// bf16 split planes for GEMM inputs: [2][rows][K]
__device__ __nv_bfloat16 g_xa[2ull*MROWS*KDIM];      // x split
__device__ __nv_bfloat16 g_ya[2ull*MROWS*KDIM];      // y split
__device__ __nv_bfloat16 g_wq[2ull*3072*KDIM];       // Wqkv^T split: [N=3072][K]
__device__ __nv_bfloat16 g_wp[2ull*1024*KDIM];       // Wproj^T split

// ---------------------------------------------------------------------------
// PTX helpers — compute_80-era ops only (harness PTX target lacks 'a' features)
// ---------------------------------------------------------------------------
__device__ __forceinline__ uint32_t smem_to_u32(const void* p) {
    uint32_t a;
    asm("{ .reg .u64 t; cvta.to.shared.u64 t, %1; cvt.u32.u64 %0, t; }"
        : "=r"(a) : "l"(p));
    return a;
}
__device__ __forceinline__ void cp16(uint32_t saddr, const void* g) {
    asm volatile("cp.async.cg.shared.global [%0], [%1], 16;"
                 :: "r"(saddr), "l"(g) : "memory");
}
__device__ __forceinline__ void ldm_x4(uint32_t (&r)[4], uint32_t addr) {
    asm volatile("ldmatrix.sync.aligned.m8n8.x4.shared.b16 {%0,%1,%2,%3}, [%4];"
        : "=r"(r[0]), "=r"(r[1]), "=r"(r[2]), "=r"(r[3]) : "r"(addr));
}
__device__ __forceinline__ void ldm_x4_t(uint32_t (&r)[4], uint32_t addr) {
    asm volatile("ldmatrix.sync.aligned.m8n8.x4.trans.shared.b16 {%0,%1,%2,%3}, [%4];"
        : "=r"(r[0]), "=r"(r[1]), "=r"(r[2]), "=r"(r[3]) : "r"(addr));
}
__device__ __forceinline__ void mma_bf16(float (&d)[4], const uint32_t (&a)[4],
                                         uint32_t b0, uint32_t b1) {
    asm volatile("mma.sync.aligned.m16n8k16.row.col.f32.bf16.bf16.f32 "
        "{%0,%1,%2,%3}, {%4,%5,%6,%7}, {%8,%9}, {%0,%1,%2,%3};"
        : "+f"(d[0]), "+f"(d[1]), "+f"(d[2]), "+f"(d[3])
        : "r"(a[0]), "r"(a[1]), "r"(a[2]), "r"(a[3]), "r"(b0), "r"(b1));
}
__device__ __forceinline__ void mma_f16(float (&d)[4], const uint32_t (&a)[4],
                                        uint32_t b0, uint32_t b1) {
    asm volatile("mma.sync.aligned.m16n8k16.row.col.f32.f16.f16.f32 "
        "{%0,%1,%2,%3}, {%4,%5,%6,%7}, {%8,%9}, {%0,%1,%2,%3};"
        : "+f"(d[0]), "+f"(d[1]), "+f"(d[2]), "+f"(d[3])
        : "r"(a[0]), "r"(a[1]), "r"(a[2]), "r"(a[3]), "r"(b0), "r"(b1));
}
// pack two fp32 into bf16x2 word: low half = lo_elem
__device__ __forceinline__ uint32_t pack_bf(float lo_elem, float hi_elem) {
    uint32_t r;
    asm("cvt.rn.bf16x2.f32 %0, %1, %2;" : "=r"(r) : "f"(hi_elem), "f"(lo_elem));
    return r;
}
// pack two fp32 into f16x2 word: low half = lo_elem
__device__ __forceinline__ uint32_t pack_hf(float lo_elem, float hi_elem) {
    __half2 h = __floats2half2_rn(lo_elem, hi_elem);
    return *(uint32_t*)&h;
}

// ---------------------------------------------------------------------------
// Conversion kernels: fp32 -> bf16 hi/lo split planes
// ---------------------------------------------------------------------------
__device__ __forceinline__ void bsplit(float x, __nv_bfloat16& h, __nv_bfloat16& l) {
    h = __float2bfloat16(x);
    l = __float2bfloat16(x - __bfloat162float(h));
}

template<int P>   // P=0: x -> g_xa ; P=1: g_y -> g_ya
__global__ __launch_bounds__(256) void conv_act(const float* __restrict__ in)
{
    __nv_bfloat16* out = P ? g_ya : g_xa;
    const float* src = P ? (const float*)g_y : in;
    const size_t i = (size_t)blockIdx.x * 256 + threadIdx.x;   // per float4
    float4 v = ((const float4*)src)[i];
    __nv_bfloat16 h[4], l[4];
    bsplit(v.x, h[0], l[0]); bsplit(v.y, h[1], l[1]);
    bsplit(v.z, h[2], l[2]); bsplit(v.w, h[3], l[3]);
    *(uint2*)(out + 4*i) = *(uint2*)h;
    *(uint2*)(out + (size_t)MROWS*KDIM + 4*i) = *(uint2*)l;
}

template<int N>   // W [K=1024][N] -> out [2][N][1024] (transposed split)
__global__ __launch_bounds__(256) void conv_w_kernel(const float* __restrict__ W)
{
    __nv_bfloat16* out = (N == 3072) ? g_wq : g_wp;
    __shared__ float t[32][33];
    const int k0 = blockIdx.x * 32, n0 = blockIdx.y * 32;
    const int tx = threadIdx.x, ty = threadIdx.y;      // 32 x 8
    #pragma unroll
    for (int i = 0; i < 4; i++)
        t[ty + 8*i][tx] = W[(size_t)(k0 + ty + 8*i) * N + n0 + tx];
    __syncthreads();
    #pragma unroll
    for (int i = 0; i < 4; i++) {
        float v = t[tx][ty + 8*i];
        __nv_bfloat16 h, l; bsplit(v, h, l);
        size_t o = (size_t)(n0 + ty + 8*i) * KDIM + k0 + tx;
        out[o] = h;
        out[(size_t)N * KDIM + o] = l;
    }
}

// ---------------------------------------------------------------------------
// mma.sync split-bf16 GEMM:  C[128x128 tile] = A[M,K] @ B[N,K]^T + bias
// 128 threads = 4 warps, warp tile 64x64 (MMA:LDSM = 96:16 per k16-step).
// MODE 0: A=g_xa, B=g_wq (N=3072), epilogue writes split q/k (bf16), v (fp16)
// MODE 1: A=g_ya, B=g_wp (N=1024), -> Out fp32
// ---------------------------------------------------------------------------
#define PLANE_BYTES 10240          // 128 * 80
#define STAGE_BYTES (4*PLANE_BYTES)
#define GEMM_SMEM_BYTES (2*STAGE_BYTES)   // 81920

template<int MODE>
__global__ __launch_bounds__(128, 2)
void mma_gemm_kernel(const float* __restrict__ bias, float* __restrict__ Out)
{
    extern __shared__ __align__(128) char smem[];
    constexpr int NT = MODE ? 1024 : 3072;
    const __nv_bfloat16* __restrict__ Ab = MODE ? g_ya : g_xa;
    const __nv_bfloat16* __restrict__ Bb = MODE ? g_wp : g_wq;
    constexpr size_t APL = (size_t)MROWS * KDIM;
    constexpr size_t BPL = (size_t)NT * KDIM;

    const int tid  = threadIdx.x;
    const int lane = tid & 31, wid = tid >> 5;
    const int row0 = blockIdx.y * 128, col0 = blockIdx.x * 128;
    const int m0w  = (wid >> 1) * 64;    // warp M offset (2x2 warp grid)
    const int n0w  = (wid & 1) * 64;     // warp N offset
    const uint32_t sb = smem_to_u32(smem);

    float acc[4][8][4];
    #pragma unroll
    for (int a = 0; a < 4; a++)
        #pragma unroll
        for (int b = 0; b < 8; b++)
            #pragma unroll
            for (int c = 0; c < 4; c++) acc[a][b][c] = 0.f;

    auto issue = [&](int st, int ck) {
        const int k0 = ck * 32;
        const uint32_t s0 = sb + st * STAGE_BYTES;
        #pragma unroll
        for (int i = 0; i < 4; i++) {
            const int c = tid + i * 128;        // 512 16B chunks per plane
            const int r = c >> 2, kc = c & 3;
            const uint32_t so = r * 80 + kc * 16;
            const __nv_bfloat16* ga = Ab + (size_t)(row0 + r) * KDIM + k0 + kc * 8;
            cp16(s0 + so,               ga);         // Ah
            cp16(s0 + PLANE_BYTES + so, ga + APL);   // Al
            const __nv_bfloat16* gb = Bb + (size_t)(col0 + r) * KDIM + k0 + kc * 8;
            cp16(s0 + 2*PLANE_BYTES + so, gb);       // Bh
            cp16(s0 + 3*PLANE_BYTES + so, gb + BPL); // Bl
        }
        asm volatile("cp.async.commit_group;" ::: "memory");
    };

    auto compute = [&](int st) {
        const uint32_t s0 = sb + st * STAGE_BYTES;
        const uint32_t rsel = (lane & 15);
        #pragma unroll
        for (int ks = 0; ks < 32; ks += 16) {
            const uint32_t coff = ks * 2 + 16 * (lane >> 4);
            uint32_t ah[4][4], al[4][4];
            #pragma unroll
            for (int mt = 0; mt < 4; mt++) {
                const uint32_t ra = s0 + (m0w + mt*16 + rsel) * 80 + coff;
                ldm_x4(ah[mt], ra);
                ldm_x4(al[mt], ra + PLANE_BYTES);
            }
            #pragma unroll
            for (int ng = 0; ng < 4; ng++) {
                const uint32_t rb = s0 + 2*PLANE_BYTES + (n0w + ng*16 + rsel) * 80 + coff;
                uint32_t bh[4], bl[4];
                ldm_x4(bh, rb);
                ldm_x4(bl, rb + PLANE_BYTES);
                #pragma unroll
                for (int mt = 0; mt < 4; mt++) {
                    mma_bf16(acc[mt][ng*2],   ah[mt], bh[0], bh[2]);   // hi*hi
                    mma_bf16(acc[mt][ng*2+1], ah[mt], bh[1], bh[3]);
                    mma_bf16(acc[mt][ng*2],   ah[mt], bl[0], bl[2]);   // hi*lo
                    mma_bf16(acc[mt][ng*2+1], ah[mt], bl[1], bl[3]);
                    mma_bf16(acc[mt][ng*2],   al[mt], bh[0], bh[2]);   // lo*hi
                    mma_bf16(acc[mt][ng*2+1], al[mt], bh[1], bh[3]);
                }
            }
        }
    };

    issue(0, 0);
    for (int ck = 0; ck < 32; ck++) {
        if (ck + 1 < 32) {
            issue((ck + 1) & 1, ck + 1);
            asm volatile("cp.async.wait_group 1;" ::: "memory");
        } else {
            asm volatile("cp.async.wait_group 0;" ::: "memory");
        }
        __syncthreads();
        compute(ck & 1);
        __syncthreads();
    }

    // ---- epilogue ----
    const int g   = lane >> 2;
    const int cql = (lane & 3) * 2;
    #pragma unroll
    for (int mt = 0; mt < 4; mt++) {
        #pragma unroll
        for (int nt = 0; nt < 8; nt++) {
            const int cg = col0 + n0w + nt * 8 + cql;
            const float b0 = bias[cg], b1 = bias[cg + 1];
            const int r0 = row0 + m0w + mt * 16 + g;
            const int r1 = r0 + 8;
            float2 lo = make_float2(acc[mt][nt][0] + b0, acc[mt][nt][1] + b1);
            float2 hi = make_float2(acc[mt][nt][2] + b0, acc[mt][nt][3] + b1);
            if (MODE == 0) {
                const int which = cg >> 10;
                const int rem = cg & (CC - 1);
                const int h = rem >> 6, d0 = rem & (DH - 1);
                uint32_t *ph, *pl;
                if (which == 0)      { ph = (uint32_t*)g_qh; pl = (uint32_t*)g_ql; }
                else if (which == 1) { ph = (uint32_t*)g_kh; pl = (uint32_t*)g_kl; }
                else                 { ph = (uint32_t*)g_vh; pl = (uint32_t*)g_vl; }
                #pragma unroll
                for (int half2i = 0; half2i < 2; half2i++) {
                    const float2 v2 = half2i ? hi : lo;
                    const int rr = half2i ? r1 : r0;
                    uint32_t hw, lw;
                    if (which == 2) {    // fp16 split for V
                        hw = pack_hf(v2.x, v2.y);
                        __half2 hh = *(__half2*)&hw;
                        lw = pack_hf(v2.x - __half2float(hh.x),
                                     v2.y - __half2float(hh.y));
                    } else {             // bf16 split for Q,K
                        hw = pack_bf(v2.x, v2.y);
                        float f0 = __uint_as_float(hw << 16);
                        float f1 = __uint_as_float(hw & 0xFFFF0000u);
                        lw = pack_bf(v2.x - f0, v2.y - f1);
                    }
                    const int bb = rr >> 11, t = rr & (TT - 1);
                    size_t off = (((size_t)(bb*NH + h)*TT + t)*DH + d0) >> 1;
                    ph[off] = hw;
                    pl[off] = lw;
                }
            } else {
                *(float2*)(Out + (size_t)r0 * CC + cg) = lo;
                *(float2*)(Out + (size_t)r1 * CC + cg) = hi;
            }
        }
    }
}

// ---------------------------------------------------------------------------
// Flash attention on mma.sync.
// QK^T: 3-term bf16 split. PV: single fp16 P x 2-term fp16 V (err ~2^-12).
// CTA = 64 q-rows of one (b,h), 4 warps (m16 each), Bc=64 per iteration.
// Smem planes: 64 rows x 144B (64 elems + 16B pad), conflict-free ldmatrix.
// ---------------------------------------------------------------------------
#define QPL 9216                     // 64 * 144
#define FL_STAGE (4*QPL)             // Kh,Kl,Vh,Vl
#define FL_SMEM_BYTES (2*QPL + 2*FL_STAGE)   // 92160

__global__ __launch_bounds__(128)
void flash_mma_kernel()
{
    extern __shared__ __align__(128) char smem[];
    const uint32_t sb = smem_to_u32(smem);
    const int tid = threadIdx.x, lane = tid & 31, wid = tid >> 5;
    const int qt = (int)gridDim.x - 1 - (int)blockIdx.x;   // heavy tiles first
    const int bh = blockIdx.y;
    const size_t base = (size_t)bh * TT * DH;

    // Q planes -> smem (part of cp.async group 0)
    {
        const __nv_bfloat16* q0 = g_qh + base + (size_t)qt * 64 * DH;
        const __nv_bfloat16* q1 = g_ql + base + (size_t)qt * 64 * DH;
        #pragma unroll
        for (int i = 0; i < 4; i++) {
            const int ch = tid + i * 128;        // 0..511
            const int r = ch >> 3, c = ch & 7;
            cp16(sb +       r*144 + c*16, q0 + r*DH + c*8);
            cp16(sb + QPL + r*144 + c*16, q1 + r*DH + c*8);
        }
    }
    const __nv_bfloat16* kh = g_kh + base;
    const __nv_bfloat16* kl = g_kl + base;
    const __half* vh = g_vh + base;
    const __half* vl = g_vl + base;

    auto issue_kv = [&](int jc, int st) {
        const uint32_t d0 = sb + 2*QPL + st*FL_STAGE;
        const size_t g0 = (size_t)jc * 64 * DH;
        #pragma unroll
        for (int i = 0; i < 4; i++) {
            const int ch = tid + i * 128;
            const int r = ch >> 3, c = ch & 7;
            const uint32_t so = r*144 + c*16;
            const size_t go = g0 + (size_t)r*DH + c*8;
            cp16(d0 +         so, kh + go);
            cp16(d0 +   QPL + so, kl + go);
            cp16(d0 + 2*QPL + so, vh + go);
            cp16(d0 + 3*QPL + so, vl + go);
        }
        asm volatile("cp.async.commit_group;" ::: "memory");
    };

    issue_kv(0, 0);   // group 0 (includes Q)

    uint32_t qfh[4][4], qfl[4][4];
    float oacc[8][4];
    #pragma unroll
    for (int nt = 0; nt < 8; nt++)
        #pragma unroll
        for (int e = 0; e < 4; e++) oacc[nt][e] = 0.f;
    float m0 = -INFINITY, m1 = -INFINITY, l0 = 0.f, l1 = 0.f;

    const int rsel = lane & 15;
    const uint32_t chalf = 16 * (lane >> 4);
    const int vrow = (lane & 7) + 8 * ((lane >> 4) & 1);
    const uint32_t vcol = 16 * ((lane >> 3) & 1);

    for (int jc = 0; jc <= qt; jc++) {
        if (jc < qt) {
            issue_kv(jc + 1, (jc + 1) & 1);
            asm volatile("cp.async.wait_group 1;" ::: "memory");
        } else {
            asm volatile("cp.async.wait_group 0;" ::: "memory");
        }
        __syncthreads();

        if (jc == 0) {   // Q fragments once
            #pragma unroll
            for (int ku = 0; ku < 4; ku++) {
                const uint32_t qa = sb + (uint32_t)((wid << 4) + rsel)*144 + ku*32 + chalf;
                ldm_x4(qfh[ku], qa);
                ldm_x4(qfl[ku], qa + QPL);
            }
        }

        const uint32_t s0 = sb + 2*QPL + (jc & 1)*FL_STAGE;

        // ---- S = Q @ K^T (3-term split) ----
        float s[8][4];
        #pragma unroll
        for (int nt = 0; nt < 8; nt++)
            #pragma unroll
            for (int e = 0; e < 4; e++) s[nt][e] = 0.f;

        #pragma unroll
        for (int ku = 0; ku < 4; ku++) {
            #pragma unroll
            for (int ng = 0; ng < 4; ng++) {
                uint32_t kh4[4], kl4[4];
                const uint32_t ka = s0 + (uint32_t)(ng*16 + rsel)*144 + ku*32 + chalf;
                ldm_x4(kh4, ka);
                ldm_x4(kl4, ka + QPL);
                mma_bf16(s[ng*2],   qfh[ku], kh4[0], kh4[2]);
                mma_bf16(s[ng*2+1], qfh[ku], kh4[1], kh4[3]);
                mma_bf16(s[ng*2],   qfh[ku], kl4[0], kl4[2]);
                mma_bf16(s[ng*2+1], qfh[ku], kl4[1], kl4[3]);
                mma_bf16(s[ng*2],   qfl[ku], kh4[0], kh4[2]);
                mma_bf16(s[ng*2+1], qfl[ku], kh4[1], kh4[3]);
            }
        }

        // ---- scale + causal mask ----
        #pragma unroll
        for (int nt = 0; nt < 8; nt++)
            #pragma unroll
            for (int e = 0; e < 4; e++) s[nt][e] *= 0.125f;
        if (jc == qt) {
            const int r0l = (wid << 4) + (lane >> 2);
            const int cb  = (lane & 3) * 2;
            #pragma unroll
            for (int nt = 0; nt < 8; nt++) {
                const int c0 = nt*8 + cb;
                if (c0     > r0l    ) s[nt][0] = -INFINITY;
                if (c0 + 1 > r0l    ) s[nt][1] = -INFINITY;
                if (c0     > r0l + 8) s[nt][2] = -INFINITY;
                if (c0 + 1 > r0l + 8) s[nt][3] = -INFINITY;
            }
        }

        // ---- online softmax (rows g and g+8; row on 4 lanes) ----
        float mx0 = -INFINITY, mx1 = -INFINITY;
        #pragma unroll
        for (int nt = 0; nt < 8; nt++) {
            mx0 = fmaxf(mx0, fmaxf(s[nt][0], s[nt][1]));
            mx1 = fmaxf(mx1, fmaxf(s[nt][2], s[nt][3]));
        }
        mx0 = fmaxf(mx0, __shfl_xor_sync(0xffffffffu, mx0, 1));
        mx0 = fmaxf(mx0, __shfl_xor_sync(0xffffffffu, mx0, 2));
        mx1 = fmaxf(mx1, __shfl_xor_sync(0xffffffffu, mx1, 1));
        mx1 = fmaxf(mx1, __shfl_xor_sync(0xffffffffu, mx1, 2));
        const float mn0 = fmaxf(m0, mx0), mn1 = fmaxf(m1, mx1);
        const float a0 = __expf(m0 - mn0), a1 = __expf(m1 - mn1);
        float sum0 = 0.f, sum1 = 0.f;
        #pragma unroll
        for (int nt = 0; nt < 8; nt++) {
            s[nt][0] = __expf(s[nt][0] - mn0); sum0 += s[nt][0];
            s[nt][1] = __expf(s[nt][1] - mn0); sum0 += s[nt][1];
            s[nt][2] = __expf(s[nt][2] - mn1); sum1 += s[nt][2];
            s[nt][3] = __expf(s[nt][3] - mn1); sum1 += s[nt][3];
        }
        sum0 += __shfl_xor_sync(0xffffffffu, sum0, 1);
        sum0 += __shfl_xor_sync(0xffffffffu, sum0, 2);
        sum1 += __shfl_xor_sync(0xffffffffu, sum1, 1);
        sum1 += __shfl_xor_sync(0xffffffffu, sum1, 2);
        l0 = l0 * a0 + sum0;  m0 = mn0;
        l1 = l1 * a1 + sum1;  m1 = mn1;
        #pragma unroll
        for (int nt = 0; nt < 8; nt++) {
            oacc[nt][0] *= a0; oacc[nt][1] *= a0;
            oacc[nt][2] *= a1; oacc[nt][3] *= a1;
        }

        // ---- O += P @ V (single fp16 P, 2-term fp16 V) ----
        #pragma unroll
        for (int u = 0; u < 4; u++) {
            uint32_t pa[4];
            #pragma unroll
            for (int t = 0; t < 4; t++) {
                const int j = 2*u + (t >> 1);
                const int e0 = (t & 1) * 2;
                pa[t] = pack_hf(s[j][e0], s[j][e0 + 1]);
            }
            #pragma unroll
            for (int dg = 0; dg < 4; dg++) {
                uint32_t vh4[4], vl4[4];
                const uint32_t va = s0 + 2*QPL + (uint32_t)(u*16 + vrow)*144 + dg*32 + vcol;
                ldm_x4_t(vh4, va);
                ldm_x4_t(vl4, va + QPL);
                mma_f16(oacc[dg*2],   pa, vh4[0], vh4[2]);
                mma_f16(oacc[dg*2+1], pa, vh4[1], vh4[3]);
                mma_f16(oacc[dg*2],   pa, vl4[0], vl4[2]);
                mma_f16(oacc[dg*2+1], pa, vl4[1], vl4[3]);
            }
        }
        __syncthreads();   // stage reads done before refill
    }

    // ---- normalize + write y [B,T,C] fp32 ----
    const int g  = lane >> 2;
    const int t2 = (lane & 3) * 2;
    const int bb = bh >> 4, hh = bh & (NH - 1);
    const int row0 = qt*64 + (wid << 4) + g;
    const float inv0 = 1.0f / l0, inv1 = 1.0f / l1;
    float* y0 = g_y + ((size_t)bb*TT + row0)*CC + hh*DH;
    float* y1 = g_y + ((size_t)bb*TT + row0 + 8)*CC + hh*DH;
    #pragma unroll
    for (int nt = 0; nt < 8; nt++) {
        *(float2*)(y0 + nt*8 + t2) = make_float2(oacc[nt][0]*inv0, oacc[nt][1]*inv0);
        *(float2*)(y1 + nt*8 + t2) = make_float2(oacc[nt][2]*inv1, oacc[nt][3]*inv1);
    }
}

// ---------------------------------------------------------------------------
extern "C" void kernel_launch(void* const* d_in, const int* in_sizes, int n_in,
                              void* d_out, int out_size)
{
    (void)in_sizes; (void)n_in; (void)out_size;
    const float* x     = (const float*)d_in[0];
    const float* Wqkv  = (const float*)d_in[1];
    const float* bqkv  = (const float*)d_in[2];
    const float* Wproj = (const float*)d_in[3];
    const float* bproj = (const float*)d_in[4];
    float* out = (float*)d_out;

    static bool attr_set = false;
    if (!attr_set) {
        cudaFuncSetAttribute(flash_mma_kernel,
            cudaFuncAttributeMaxDynamicSharedMemorySize, FL_SMEM_BYTES);
        cudaFuncSetAttribute(mma_gemm_kernel<0>,
            cudaFuncAttributeMaxDynamicSharedMemorySize, GEMM_SMEM_BYTES);
        cudaFuncSetAttribute(mma_gemm_kernel<1>,
            cudaFuncAttributeMaxDynamicSharedMemorySize, GEMM_SMEM_BYTES);
        attr_set = true;
    }

    const int act4 = (MROWS * KDIM) / 4;

    // 0) splits: x -> g_xa ; Wqkv -> g_wq ; Wproj -> g_wp
    conv_act<0><<<act4 / 256, 256>>>(x);
    conv_w_kernel<3072><<<dim3(KDIM/32, 3072/32), dim3(32, 8)>>>(Wqkv);
    conv_w_kernel<1024><<<dim3(KDIM/32, 1024/32), dim3(32, 8)>>>(Wproj);

    // 1) QKV projection -> split q/k (bf16), v (fp16), [B,H,T,D]
    mma_gemm_kernel<0><<<dim3(3072/128, MROWS/128), 128, GEMM_SMEM_BYTES>>>(bqkv, nullptr);

    // 2) causal flash attention (tensor cores) -> g_y [B,T,C]
    flash_mma_kernel<<<dim3(TT/64, NB*NH), 128, FL_SMEM_BYTES>>>();

    // 3) y split + output projection -> d_out
    conv_act<1><<<act4 / 256, 256>>>(nullptr);
    mma_gemm_kernel<1><<<dim3(1024/128, MROWS/128), 128, GEMM_SMEM_BYTES>>>(bproj, out);
}

// round 12
// speedup vs baseline: 1.2692x; 1.2692x over previous
#include <cuda_runtime.h>
#include <cuda_bf16.h>
#include <cuda_fp16.h>
#include <math.h>
#include <stdint.h>

#define NB 4
#define NH 16
#define TT 2048
#define DH 64
#define CC 1024
#define MROWS (NB*TT)   // 8192
#define KDIM  1024

// ---------------------------------------------------------------------------
// Scratch (__device__ globals; allocation-free rule)
// ---------------------------------------------------------------------------
__device__ float g_y[MROWS*CC];      // [B,T,C] fp32 attention output

// q: single fp16 plane; k,v: fp16 hi+lo planes; all [B,H,T,D]
__device__ __half g_qf[NB*NH*TT*DH];
__device__ __half g_kf[NB*NH*TT*DH];
__device__ __half g_kl[NB*NH*TT*DH];
__device__ __half g_vh[NB*NH*TT*DH];
__device__ __half g_vl[NB*NH*TT*DH];

// QKV GEMM inputs: x single fp16 plane; Wqkv^T fp16 hi+lo [2][3072][K]
__device__ __half g_xf[(size_t)MROWS*KDIM];
__device__ __half g_wqf[2ull*3072*KDIM];

// Proj GEMM inputs (3-term bf16 anchor): y split, Wproj^T split
__device__ __nv_bfloat16 g_ya[2ull*MROWS*KDIM];
__device__ __nv_bfloat16 g_wp[2ull*1024*KDIM];

// ---------------------------------------------------------------------------
// PTX helpers — compute_80-era ops only (harness PTX target lacks 'a' features)
// ---------------------------------------------------------------------------
__device__ __forceinline__ uint32_t smem_to_u32(const void* p) {
    uint32_t a;
    asm("{ .reg .u64 t; cvta.to.shared.u64 t, %1; cvt.u32.u64 %0, t; }"
        : "=r"(a) : "l"(p));
    return a;
}
__device__ __forceinline__ void cp16(uint32_t saddr, const void* g) {
    asm volatile("cp.async.cg.shared.global [%0], [%1], 16;"
                 :: "r"(saddr), "l"(g) : "memory");
}
__device__ __forceinline__ void ldm_x4(uint32_t (&r)[4], uint32_t addr) {
    asm volatile("ldmatrix.sync.aligned.m8n8.x4.shared.b16 {%0,%1,%2,%3}, [%4];"
        : "=r"(r[0]), "=r"(r[1]), "=r"(r[2]), "=r"(r[3]) : "r"(addr));
}
__device__ __forceinline__ void ldm_x4_t(uint32_t (&r)[4], uint32_t addr) {
    asm volatile("ldmatrix.sync.aligned.m8n8.x4.trans.shared.b16 {%0,%1,%2,%3}, [%4];"
        : "=r"(r[0]), "=r"(r[1]), "=r"(r[2]), "=r"(r[3]) : "r"(addr));
}
__device__ __forceinline__ void mma_bf16(float (&d)[4], const uint32_t (&a)[4],
                                         uint32_t b0, uint32_t b1) {
    asm volatile("mma.sync.aligned.m16n8k16.row.col.f32.bf16.bf16.f32 "
        "{%0,%1,%2,%3}, {%4,%5,%6,%7}, {%8,%9}, {%0,%1,%2,%3};"
        : "+f"(d[0]), "+f"(d[1]), "+f"(d[2]), "+f"(d[3])
        : "r"(a[0]), "r"(a[1]), "r"(a[2]), "r"(a[3]), "r"(b0), "r"(b1));
}
__device__ __forceinline__ void mma_f16(float (&d)[4], const uint32_t (&a)[4],
                                        uint32_t b0, uint32_t b1) {
    asm volatile("mma.sync.aligned.m16n8k16.row.col.f32.f16.f16.f32 "
        "{%0,%1,%2,%3}, {%4,%5,%6,%7}, {%8,%9}, {%0,%1,%2,%3};"
        : "+f"(d[0]), "+f"(d[1]), "+f"(d[2]), "+f"(d[3])
        : "r"(a[0]), "r"(a[1]), "r"(a[2]), "r"(a[3]), "r"(b0), "r"(b1));
}
// pack two fp32 into f16x2 word: low half = lo_elem
__device__ __forceinline__ uint32_t pack_hf(float lo_elem, float hi_elem) {
    __half2 h = __floats2half2_rn(lo_elem, hi_elem);
    return *(uint32_t*)&h;
}

// ---------------------------------------------------------------------------
// Conversion kernels
// ---------------------------------------------------------------------------
__device__ __forceinline__ void bsplit(float x, __nv_bfloat16& h, __nv_bfloat16& l) {
    h = __float2bfloat16(x);
    l = __float2bfloat16(x - __bfloat162float(h));
}
__device__ __forceinline__ void hsplit(float x, __half& h, __half& l) {
    h = __float2half_rn(x);
    l = __float2half_rn(x - __half2float(h));
}

// x -> g_xf (single fp16 plane)
__global__ __launch_bounds__(256) void conv_x(const float* __restrict__ in)
{
    const size_t i = (size_t)blockIdx.x * 256 + threadIdx.x;   // per float4
    float4 v = ((const float4*)in)[i];
    __half h[4];
    h[0] = __float2half_rn(v.x); h[1] = __float2half_rn(v.y);
    h[2] = __float2half_rn(v.z); h[3] = __float2half_rn(v.w);
    *(uint2*)(g_xf + 4*i) = *(uint2*)h;
}

// g_y -> g_ya (bf16 hi/lo split planes, for proj)
__global__ __launch_bounds__(256) void conv_y()
{
    const size_t i = (size_t)blockIdx.x * 256 + threadIdx.x;
    float4 v = ((const float4*)g_y)[i];
    __nv_bfloat16 h[4], l[4];
    bsplit(v.x, h[0], l[0]); bsplit(v.y, h[1], l[1]);
    bsplit(v.z, h[2], l[2]); bsplit(v.w, h[3], l[3]);
    *(uint2*)(g_ya + 4*i) = *(uint2*)h;
    *(uint2*)(g_ya + (size_t)MROWS*KDIM + 4*i) = *(uint2*)l;
}

// Wqkv [K][3072] -> g_wqf [2][3072][K] (fp16 transposed split)
__global__ __launch_bounds__(256) void conv_w_qkv(const float* __restrict__ W)
{
    constexpr int N = 3072;
    __shared__ float t[32][33];
    const int k0 = blockIdx.x * 32, n0 = blockIdx.y * 32;
    const int tx = threadIdx.x, ty = threadIdx.y;      // 32 x 8
    #pragma unroll
    for (int i = 0; i < 4; i++)
        t[ty + 8*i][tx] = W[(size_t)(k0 + ty + 8*i) * N + n0 + tx];
    __syncthreads();
    #pragma unroll
    for (int i = 0; i < 4; i++) {
        float v = t[tx][ty + 8*i];
        __half h, l; hsplit(v, h, l);
        size_t o = (size_t)(n0 + ty + 8*i) * KDIM + k0 + tx;
        g_wqf[o] = h;
        g_wqf[(size_t)N * KDIM + o] = l;
    }
}

// Wproj [K][1024] -> g_wp [2][1024][K] (bf16 transposed split)
__global__ __launch_bounds__(256) void conv_w_proj(const float* __restrict__ W)
{
    constexpr int N = 1024;
    __shared__ float t[32][33];
    const int k0 = blockIdx.x * 32, n0 = blockIdx.y * 32;
    const int tx = threadIdx.x, ty = threadIdx.y;
    #pragma unroll
    for (int i = 0; i < 4; i++)
        t[ty + 8*i][tx] = W[(size_t)(k0 + ty + 8*i) * N + n0 + tx];
    __syncthreads();
    #pragma unroll
    for (int i = 0; i < 4; i++) {
        float v = t[tx][ty + 8*i];
        __nv_bfloat16 h, l; bsplit(v, h, l);
        size_t o = (size_t)(n0 + ty + 8*i) * KDIM + k0 + tx;
        g_wp[o] = h;
        g_wp[(size_t)N * KDIM + o] = l;
    }
}

#define PLANE_BYTES 10240          // 128 rows * 80 B (32 elems*2B + 16B pad)

// ---------------------------------------------------------------------------
// QKV GEMM, 2-term fp16: C = x @ Wqkv + b;  A 1 plane, B hi+lo.
// 256 threads, 8 warps, warp tile 32x64 (R9-proven shape), dbl-buffered BK=32.
// Stage layout: [A][Bh][Bl] = 3 planes. Epilogue -> q (fp16), k/v (fp16 hi+lo).
// ---------------------------------------------------------------------------
#define QKV_STAGE (3*PLANE_BYTES)
#define QKV_SMEM  (2*QKV_STAGE)    // 61440

__global__ __launch_bounds__(256, 2)
void qkv_gemm_kernel(const float* __restrict__ bias)
{
    extern __shared__ __align__(128) char smem[];
    constexpr int NT = 3072;
    constexpr size_t BPL = (size_t)NT * KDIM;

    const int tid  = threadIdx.x;
    const int lane = tid & 31, wid = tid >> 5;
    const int row0 = blockIdx.y * 128, col0 = blockIdx.x * 128;
    const int m0w  = (wid >> 1) * 32;
    const int n0w  = (wid & 1) * 64;
    const uint32_t sb = smem_to_u32(smem);

    float acc[2][8][4];
    #pragma unroll
    for (int a = 0; a < 2; a++)
        #pragma unroll
        for (int b = 0; b < 8; b++)
            #pragma unroll
            for (int c = 0; c < 4; c++) acc[a][b][c] = 0.f;

    auto issue = [&](int st, int ck) {
        const int k0 = ck * 32;
        const uint32_t s0 = sb + st * QKV_STAGE;
        #pragma unroll
        for (int i = 0; i < 2; i++) {
            const int c = tid + i * 256;       // 512 16B chunks per plane
            const int r = c >> 2, kc = c & 3;
            const uint32_t so = r * 80 + kc * 16;
            cp16(s0 + so, g_xf + (size_t)(row0 + r) * KDIM + k0 + kc * 8);
            const __half* gb = g_wqf + (size_t)(col0 + r) * KDIM + k0 + kc * 8;
            cp16(s0 + PLANE_BYTES   + so, gb);        // Bh
            cp16(s0 + 2*PLANE_BYTES + so, gb + BPL);  // Bl
        }
        asm volatile("cp.async.commit_group;" ::: "memory");
    };

    auto compute = [&](int st) {
        const uint32_t s0 = sb + st * QKV_STAGE;
        const uint32_t rsel = (lane & 15);
        #pragma unroll
        for (int ks = 0; ks < 32; ks += 16) {
            const uint32_t coff = ks * 2 + 16 * (lane >> 4);
            uint32_t af[2][4];
            #pragma unroll
            for (int mt = 0; mt < 2; mt++)
                ldm_x4(af[mt], s0 + (m0w + mt*16 + rsel) * 80 + coff);
            #pragma unroll
            for (int nt = 0; nt < 4; nt++) {
                const uint32_t rb = s0 + PLANE_BYTES + (n0w + nt*16 + rsel) * 80 + coff;
                uint32_t bh[4], bl[4];
                ldm_x4(bh, rb);
                ldm_x4(bl, rb + PLANE_BYTES);
                #pragma unroll
                for (int mt = 0; mt < 2; mt++) {
                    mma_f16(acc[mt][nt*2],   af[mt], bh[0], bh[2]);
                    mma_f16(acc[mt][nt*2+1], af[mt], bh[1], bh[3]);
                    mma_f16(acc[mt][nt*2],   af[mt], bl[0], bl[2]);
                    mma_f16(acc[mt][nt*2+1], af[mt], bl[1], bl[3]);
                }
            }
        }
    };

    issue(0, 0);
    for (int ck = 0; ck < 32; ck++) {
        if (ck + 1 < 32) {
            issue((ck + 1) & 1, ck + 1);
            asm volatile("cp.async.wait_group 1;" ::: "memory");
        } else {
            asm volatile("cp.async.wait_group 0;" ::: "memory");
        }
        __syncthreads();
        compute(ck & 1);
        __syncthreads();
    }

    // ---- epilogue: + bias, split-convert, scatter to [B,H,T,D] ----
    const int g   = lane >> 2;
    const int cql = (lane & 3) * 2;
    #pragma unroll
    for (int mt = 0; mt < 2; mt++) {
        #pragma unroll
        for (int nt = 0; nt < 8; nt++) {
            const int cg = col0 + n0w + nt * 8 + cql;
            const float b0 = bias[cg], b1 = bias[cg + 1];
            const int r0 = row0 + m0w + mt * 16 + g;
            const int which = cg >> 10;
            const int rem = cg & (CC - 1);
            const int h = rem >> 6, d0 = rem & (DH - 1);
            #pragma unroll
            for (int half2i = 0; half2i < 2; half2i++) {
                const float vx = acc[mt][nt][half2i*2]   + b0;
                const float vy = acc[mt][nt][half2i*2+1] + b1;
                const int rr = r0 + half2i * 8;
                const int bb = rr >> 11, t = rr & (TT - 1);
                const size_t off = (((size_t)(bb*NH + h)*TT + t)*DH + d0) >> 1;
                const uint32_t hw = pack_hf(vx, vy);
                if (which == 0) {
                    ((uint32_t*)g_qf)[off] = hw;
                } else {
                    __half2 hh = *(__half2*)&hw;
                    const uint32_t lw = pack_hf(vx - __half2float(hh.x),
                                                vy - __half2float(hh.y));
                    uint32_t* ph = (which == 1) ? (uint32_t*)g_kf : (uint32_t*)g_vh;
                    uint32_t* pl = (which == 1) ? (uint32_t*)g_kl : (uint32_t*)g_vl;
                    ph[off] = hw;
                    pl[off] = lw;
                }
            }
        }
    }
}

// ---------------------------------------------------------------------------
// Proj GEMM, 3-term bf16 (precision anchor): Out = y @ Wproj + b.
// Identical structure to R9 MODE 1. Stage: [Ah][Al][Bh][Bl] = 4 planes.
// ---------------------------------------------------------------------------
#define PROJ_STAGE (4*PLANE_BYTES)
#define PROJ_SMEM  (2*PROJ_STAGE)   // 81920

__global__ __launch_bounds__(256, 2)
void proj_gemm_kernel(const float* __restrict__ bias, float* __restrict__ Out)
{
    extern __shared__ __align__(128) char smem[];
    constexpr int NT = 1024;
    constexpr size_t APL = (size_t)MROWS * KDIM;
    constexpr size_t BPL = (size_t)NT * KDIM;

    const int tid  = threadIdx.x;
    const int lane = tid & 31, wid = tid >> 5;
    const int row0 = blockIdx.y * 128, col0 = blockIdx.x * 128;
    const int m0w  = (wid >> 1) * 32;
    const int n0w  = (wid & 1) * 64;
    const uint32_t sb = smem_to_u32(smem);

    float acc[2][8][4];
    #pragma unroll
    for (int a = 0; a < 2; a++)
        #pragma unroll
        for (int b = 0; b < 8; b++)
            #pragma unroll
            for (int c = 0; c < 4; c++) acc[a][b][c] = 0.f;

    auto issue = [&](int st, int ck) {
        const int k0 = ck * 32;
        const uint32_t s0 = sb + st * PROJ_STAGE;
        #pragma unroll
        for (int i = 0; i < 2; i++) {
            const int c = tid + i * 256;
            const int r = c >> 2, kc = c & 3;
            const uint32_t so = r * 80 + kc * 16;
            const __nv_bfloat16* ga = g_ya + (size_t)(row0 + r) * KDIM + k0 + kc * 8;
            cp16(s0 + so,               ga);
            cp16(s0 + PLANE_BYTES + so, ga + APL);
            const __nv_bfloat16* gb = g_wp + (size_t)(col0 + r) * KDIM + k0 + kc * 8;
            cp16(s0 + 2*PLANE_BYTES + so, gb);
            cp16(s0 + 3*PLANE_BYTES + so, gb + BPL);
        }
        asm volatile("cp.async.commit_group;" ::: "memory");
    };

    auto compute = [&](int st) {
        const uint32_t s0 = sb + st * PROJ_STAGE;
        const uint32_t rsel = (lane & 15);
        #pragma unroll
        for (int ks = 0; ks < 32; ks += 16) {
            const uint32_t coff = ks * 2 + 16 * (lane >> 4);
            uint32_t ah[2][4], al[2][4];
            #pragma unroll
            for (int mt = 0; mt < 2; mt++) {
                const uint32_t ra = s0 + (m0w + mt*16 + rsel) * 80 + coff;
                ldm_x4(ah[mt], ra);
                ldm_x4(al[mt], ra + PLANE_BYTES);
            }
            #pragma unroll
            for (int nt = 0; nt < 4; nt++) {
                const uint32_t rb = s0 + 2*PLANE_BYTES + (n0w + nt*16 + rsel) * 80 + coff;
                uint32_t bh[4], bl[4];
                ldm_x4(bh, rb);
                ldm_x4(bl, rb + PLANE_BYTES);
                #pragma unroll
                for (int mt = 0; mt < 2; mt++) {
                    mma_bf16(acc[mt][nt*2],   ah[mt], bh[0], bh[2]);
                    mma_bf16(acc[mt][nt*2+1], ah[mt], bh[1], bh[3]);
                    mma_bf16(acc[mt][nt*2],   ah[mt], bl[0], bl[2]);
                    mma_bf16(acc[mt][nt*2+1], ah[mt], bl[1], bl[3]);
                    mma_bf16(acc[mt][nt*2],   al[mt], bh[0], bh[2]);
                    mma_bf16(acc[mt][nt*2+1], al[mt], bh[1], bh[3]);
                }
            }
        }
    };

    issue(0, 0);
    for (int ck = 0; ck < 32; ck++) {
        if (ck + 1 < 32) {
            issue((ck + 1) & 1, ck + 1);
            asm volatile("cp.async.wait_group 1;" ::: "memory");
        } else {
            asm volatile("cp.async.wait_group 0;" ::: "memory");
        }
        __syncthreads();
        compute(ck & 1);
        __syncthreads();
    }

    const int g   = lane >> 2;
    const int cql = (lane & 3) * 2;
    #pragma unroll
    for (int mt = 0; mt < 2; mt++) {
        #pragma unroll
        for (int nt = 0; nt < 8; nt++) {
            const int cg = col0 + n0w + nt * 8 + cql;
            const float b0 = bias[cg], b1 = bias[cg + 1];
            const int r0 = row0 + m0w + mt * 16 + g;
            *(float2*)(Out + (size_t)r0 * CC + cg) =
                make_float2(acc[mt][nt][0] + b0, acc[mt][nt][1] + b1);
            *(float2*)(Out + (size_t)(r0 + 8) * CC + cg) =
                make_float2(acc[mt][nt][2] + b0, acc[mt][nt][3] + b1);
        }
    }
}

// ---------------------------------------------------------------------------
// Flash attention on mma.sync, all fp16:
// QK^T: Q 1 plane x K hi+lo (2 terms). PV: P fp16 x V hi+lo (2 terms).
// CTA = 64 q-rows of one (b,h), 4 warps, Bc=64.
// Smem: Q 1 plane + 2 stages x [Kh,Kl,Vh,Vl].
// ---------------------------------------------------------------------------
#define QPL 9216                     // 64 * 144
#define FL_STAGE (4*QPL)
#define FL_SMEM_BYTES (QPL + 2*FL_STAGE)   // 82944

__global__ __launch_bounds__(128)
void flash_mma_kernel()
{
    extern __shared__ __align__(128) char smem[];
    const uint32_t sb = smem_to_u32(smem);
    const int tid = threadIdx.x, lane = tid & 31, wid = tid >> 5;
    const int qt = (int)gridDim.x - 1 - (int)blockIdx.x;   // heavy tiles first
    const int bh = blockIdx.y;
    const size_t base = (size_t)bh * TT * DH;

    // Q plane -> smem (part of cp.async group 0)
    {
        const __half* q0 = g_qf + base + (size_t)qt * 64 * DH;
        #pragma unroll
        for (int i = 0; i < 4; i++) {
            const int ch = tid + i * 128;        // 512 chunks
            const int r = ch >> 3, c = ch & 7;
            cp16(sb + r*144 + c*16, q0 + r*DH + c*8);
        }
    }
    const __half* kh = g_kf + base;
    const __half* kl = g_kl + base;
    const __half* vh = g_vh + base;
    const __half* vl = g_vl + base;

    auto issue_kv = [&](int jc, int st) {
        const uint32_t d0 = sb + QPL + st*FL_STAGE;
        const size_t g0 = (size_t)jc * 64 * DH;
        #pragma unroll
        for (int i = 0; i < 4; i++) {
            const int ch = tid + i * 128;
            const int r = ch >> 3, c = ch & 7;
            const uint32_t so = r*144 + c*16;
            const size_t go = g0 + (size_t)r*DH + c*8;
            cp16(d0 +         so, kh + go);
            cp16(d0 +   QPL + so, kl + go);
            cp16(d0 + 2*QPL + so, vh + go);
            cp16(d0 + 3*QPL + so, vl + go);
        }
        asm volatile("cp.async.commit_group;" ::: "memory");
    };

    issue_kv(0, 0);   // group 0 (includes Q)

    uint32_t qf[4][4];
    float oacc[8][4];
    #pragma unroll
    for (int nt = 0; nt < 8; nt++)
        #pragma unroll
        for (int e = 0; e < 4; e++) oacc[nt][e] = 0.f;
    float m0 = -INFINITY, m1 = -INFINITY, l0 = 0.f, l1 = 0.f;

    const int rsel = lane & 15;
    const uint32_t chalf = 16 * (lane >> 4);
    const int vrow = (lane & 7) + 8 * ((lane >> 4) & 1);
    const uint32_t vcol = 16 * ((lane >> 3) & 1);

    for (int jc = 0; jc <= qt; jc++) {
        if (jc < qt) {
            issue_kv(jc + 1, (jc + 1) & 1);
            asm volatile("cp.async.wait_group 1;" ::: "memory");
        } else {
            asm volatile("cp.async.wait_group 0;" ::: "memory");
        }
        __syncthreads();

        if (jc == 0) {   // Q fragments once
            #pragma unroll
            for (int ku = 0; ku < 4; ku++)
                ldm_x4(qf[ku], sb + (uint32_t)((wid << 4) + rsel)*144 + ku*32 + chalf);
        }

        const uint32_t s0 = sb + QPL + (jc & 1)*FL_STAGE;

        // ---- S = Q @ K^T (2-term fp16) ----
        float s[8][4];
        #pragma unroll
        for (int nt = 0; nt < 8; nt++)
            #pragma unroll
            for (int e = 0; e < 4; e++) s[nt][e] = 0.f;

        #pragma unroll
        for (int ku = 0; ku < 4; ku++) {
            #pragma unroll
            for (int ng = 0; ng < 4; ng++) {
                uint32_t kh4[4], kl4[4];
                const uint32_t ka = s0 + (uint32_t)(ng*16 + rsel)*144 + ku*32 + chalf;
                ldm_x4(kh4, ka);
                ldm_x4(kl4, ka + QPL);
                mma_f16(s[ng*2],   qf[ku], kh4[0], kh4[2]);
                mma_f16(s[ng*2+1], qf[ku], kh4[1], kh4[3]);
                mma_f16(s[ng*2],   qf[ku], kl4[0], kl4[2]);
                mma_f16(s[ng*2+1], qf[ku], kl4[1], kl4[3]);
            }
        }

        // ---- scale + causal mask ----
        #pragma unroll
        for (int nt = 0; nt < 8; nt++)
            #pragma unroll
            for (int e = 0; e < 4; e++) s[nt][e] *= 0.125f;
        if (jc == qt) {
            const int r0l = (wid << 4) + (lane >> 2);
            const int cb  = (lane & 3) * 2;
            #pragma unroll
            for (int nt = 0; nt < 8; nt++) {
                const int c0 = nt*8 + cb;
                if (c0     > r0l    ) s[nt][0] = -INFINITY;
                if (c0 + 1 > r0l    ) s[nt][1] = -INFINITY;
                if (c0     > r0l + 8) s[nt][2] = -INFINITY;
                if (c0 + 1 > r0l + 8) s[nt][3] = -INFINITY;
            }
        }

        // ---- online softmax (rows g and g+8; row on 4 lanes) ----
        float mx0 = -INFINITY, mx1 = -INFINITY;
        #pragma unroll
        for (int nt = 0; nt < 8; nt++) {
            mx0 = fmaxf(mx0, fmaxf(s[nt][0], s[nt][1]));
            mx1 = fmaxf(mx1, fmaxf(s[nt][2], s[nt][3]));
        }
        mx0 = fmaxf(mx0, __shfl_xor_sync(0xffffffffu, mx0, 1));
        mx0 = fmaxf(mx0, __shfl_xor_sync(0xffffffffu, mx0, 2));
        mx1 = fmaxf(mx1, __shfl_xor_sync(0xffffffffu, mx1, 1));
        mx1 = fmaxf(mx1, __shfl_xor_sync(0xffffffffu, mx1, 2));
        const float mn0 = fmaxf(m0, mx0), mn1 = fmaxf(m1, mx1);
        const float a0 = __expf(m0 - mn0), a1 = __expf(m1 - mn1);
        float sum0 = 0.f, sum1 = 0.f;
        #pragma unroll
        for (int nt = 0; nt < 8; nt++) {
            s[nt][0] = __expf(s[nt][0] - mn0); sum0 += s[nt][0];
            s[nt][1] = __expf(s[nt][1] - mn0); sum0 += s[nt][1];
            s[nt][2] = __expf(s[nt][2] - mn1); sum1 += s[nt][2];
            s[nt][3] = __expf(s[nt][3] - mn1); sum1 += s[nt][3];
        }
        sum0 += __shfl_xor_sync(0xffffffffu, sum0, 1);
        sum0 += __shfl_xor_sync(0xffffffffu, sum0, 2);
        sum1 += __shfl_xor_sync(0xffffffffu, sum1, 1);
        sum1 += __shfl_xor_sync(0xffffffffu, sum1, 2);
        l0 = l0 * a0 + sum0;  m0 = mn0;
        l1 = l1 * a1 + sum1;  m1 = mn1;
        #pragma unroll
        for (int nt = 0; nt < 8; nt++) {
            oacc[nt][0] *= a0; oacc[nt][1] *= a0;
            oacc[nt][2] *= a1; oacc[nt][3] *= a1;
        }

        // ---- O += P @ V (fp16 P, 2-term fp16 V) ----
        #pragma unroll
        for (int u = 0; u < 4; u++) {
            uint32_t pa[4];
            #pragma unroll
            for (int t = 0; t < 4; t++) {
                const int j = 2*u + (t >> 1);
                const int e0 = (t & 1) * 2;
                pa[t] = pack_hf(s[j][e0], s[j][e0 + 1]);
            }
            #pragma unroll
            for (int dg = 0; dg < 4; dg++) {
                uint32_t vh4[4], vl4[4];
                const uint32_t va = s0 + 2*QPL + (uint32_t)(u*16 + vrow)*144 + dg*32 + vcol;
                ldm_x4_t(vh4, va);
                ldm_x4_t(vl4, va + QPL);
                mma_f16(oacc[dg*2],   pa, vh4[0], vh4[2]);
                mma_f16(oacc[dg*2+1], pa, vh4[1], vh4[3]);
                mma_f16(oacc[dg*2],   pa, vl4[0], vl4[2]);
                mma_f16(oacc[dg*2+1], pa, vl4[1], vl4[3]);
            }
        }
        __syncthreads();   // stage reads done before refill
    }

    // ---- normalize + write y [B,T,C] fp32 ----
    const int g  = lane >> 2;
    const int t2 = (lane & 3) * 2;
    const int bb = bh >> 4, hh = bh & (NH - 1);
    const int row0 = qt*64 + (wid << 4) + g;
    const float inv0 = 1.0f / l0, inv1 = 1.0f / l1;
    float* y0 = g_y + ((size_t)bb*TT + row0)*CC + hh*DH;
    float* y1 = g_y + ((size_t)bb*TT + row0 + 8)*CC + hh*DH;
    #pragma unroll
    for (int nt = 0; nt < 8; nt++) {
        *(float2*)(y0 + nt*8 + t2) = make_float2(oacc[nt][0]*inv0, oacc[nt][1]*inv0);
        *(float2*)(y1 + nt*8 + t2) = make_float2(oacc[nt][2]*inv1, oacc[nt][3]*inv1);
    }
}

// ---------------------------------------------------------------------------
extern "C" void kernel_launch(void* const* d_in, const int* in_sizes, int n_in,
                              void* d_out, int out_size)
{
    (void)in_sizes; (void)n_in; (void)out_size;
    const float* x     = (const float*)d_in[0];
    const float* Wqkv  = (const float*)d_in[1];
    const float* bqkv  = (const float*)d_in[2];
    const float* Wproj = (const float*)d_in[3];
    const float* bproj = (const float*)d_in[4];
    float* out = (float*)d_out;

    static bool attr_set = false;
    if (!attr_set) {
        cudaFuncSetAttribute(flash_mma_kernel,
            cudaFuncAttributeMaxDynamicSharedMemorySize, FL_SMEM_BYTES);
        cudaFuncSetAttribute(qkv_gemm_kernel,
            cudaFuncAttributeMaxDynamicSharedMemorySize, QKV_SMEM);
        cudaFuncSetAttribute(proj_gemm_kernel,
            cudaFuncAttributeMaxDynamicSharedMemorySize, PROJ_SMEM);
        attr_set = true;
    }

    const int act4 = (MROWS * KDIM) / 4;

    // 0) conversions
    conv_x<<<act4 / 256, 256>>>(x);
    conv_w_qkv<<<dim3(KDIM/32, 3072/32), dim3(32, 8)>>>(Wqkv);
    conv_w_proj<<<dim3(KDIM/32, 1024/32), dim3(32, 8)>>>(Wproj);

    // 1) QKV projection (fp16 2-term) -> q fp16, k/v fp16 hi+lo [B,H,T,D]
    qkv_gemm_kernel<<<dim3(3072/128, MROWS/128), 256, QKV_SMEM>>>(bqkv);

    // 2) causal flash attention (tensor cores) -> g_y [B,T,C]
    flash_mma_kernel<<<dim3(TT/64, NB*NH), 128, FL_SMEM_BYTES>>>();

    // 3) y split + output projection (bf16 3-term anchor) -> d_out
    conv_y<<<act4 / 256, 256>>>();
    proj_gemm_kernel<<<dim3(1024/128, MROWS/128), 256, PROJ_SMEM>>>(bproj, out);
}

// round 13
// speedup vs baseline: 1.4455x; 1.1389x over previous
#include <cuda_runtime.h>
#include <cuda_bf16.h>
#include <cuda_fp16.h>
#include <math.h>
#include <stdint.h>

#define NB 4
#define NH 16
#define TT 2048
#define DH 64
#define CC 1024
#define MROWS (NB*TT)   // 8192
#define KDIM  1024

// ---------------------------------------------------------------------------
// Scratch (__device__ globals; allocation-free rule)
// ---------------------------------------------------------------------------
// q: single fp16 plane; k,v: fp16 hi+lo planes; all [B,H,T,D]
__device__ __half g_qf[NB*NH*TT*DH];
__device__ __half g_kf[NB*NH*TT*DH];
__device__ __half g_kl[NB*NH*TT*DH];
__device__ __half g_vh[NB*NH*TT*DH];
__device__ __half g_vl[NB*NH*TT*DH];

// y (attention out) single fp16 plane [B,T,C], written by flash epilogue
__device__ __half g_yf[(size_t)MROWS*KDIM];

// GEMM weights/inputs
__device__ __half g_xf[(size_t)MROWS*KDIM];      // x single fp16 plane
__device__ __half g_wqf[2ull*3072*KDIM];         // Wqkv^T fp16 hi+lo
__device__ __half g_wpf[2ull*1024*KDIM];         // Wproj^T fp16 hi+lo

// ---------------------------------------------------------------------------
// PTX helpers — compute_80-era ops only (harness PTX target lacks 'a' features)
// ---------------------------------------------------------------------------
__device__ __forceinline__ uint32_t smem_to_u32(const void* p) {
    uint32_t a;
    asm("{ .reg .u64 t; cvta.to.shared.u64 t, %1; cvt.u32.u64 %0, t; }"
        : "=r"(a) : "l"(p));
    return a;
}
__device__ __forceinline__ void cp16(uint32_t saddr, const void* g) {
    asm volatile("cp.async.cg.shared.global [%0], [%1], 16;"
                 :: "r"(saddr), "l"(g) : "memory");
}
__device__ __forceinline__ void ldm_x4(uint32_t (&r)[4], uint32_t addr) {
    asm volatile("ldmatrix.sync.aligned.m8n8.x4.shared.b16 {%0,%1,%2,%3}, [%4];"
        : "=r"(r[0]), "=r"(r[1]), "=r"(r[2]), "=r"(r[3]) : "r"(addr));
}
__device__ __forceinline__ void ldm_x4_t(uint32_t (&r)[4], uint32_t addr) {
    asm volatile("ldmatrix.sync.aligned.m8n8.x4.trans.shared.b16 {%0,%1,%2,%3}, [%4];"
        : "=r"(r[0]), "=r"(r[1]), "=r"(r[2]), "=r"(r[3]) : "r"(addr));
}
__device__ __forceinline__ void mma_f16(float (&d)[4], const uint32_t (&a)[4],
                                        uint32_t b0, uint32_t b1) {
    asm volatile("mma.sync.aligned.m16n8k16.row.col.f32.f16.f16.f32 "
        "{%0,%1,%2,%3}, {%4,%5,%6,%7}, {%8,%9}, {%0,%1,%2,%3};"
        : "+f"(d[0]), "+f"(d[1]), "+f"(d[2]), "+f"(d[3])
        : "r"(a[0]), "r"(a[1]), "r"(a[2]), "r"(a[3]), "r"(b0), "r"(b1));
}
// pack two fp32 into f16x2 word: low half = lo_elem
__device__ __forceinline__ uint32_t pack_hf(float lo_elem, float hi_elem) {
    __half2 h = __floats2half2_rn(lo_elem, hi_elem);
    return *(uint32_t*)&h;
}

// ---------------------------------------------------------------------------
// Conversion kernels
// ---------------------------------------------------------------------------
__device__ __forceinline__ void hsplit(float x, __half& h, __half& l) {
    h = __float2half_rn(x);
    l = __float2half_rn(x - __half2float(h));
}

// x -> g_xf (single fp16 plane)
__global__ __launch_bounds__(256) void conv_x(const float* __restrict__ in)
{
    const size_t i = (size_t)blockIdx.x * 256 + threadIdx.x;   // per float4
    float4 v = ((const float4*)in)[i];
    __half h[4];
    h[0] = __float2half_rn(v.x); h[1] = __float2half_rn(v.y);
    h[2] = __float2half_rn(v.z); h[3] = __float2half_rn(v.w);
    *(uint2*)(g_xf + 4*i) = *(uint2*)h;
}

// W [K][N] -> out [2][N][K] (fp16 transposed split)
template<int N>
__global__ __launch_bounds__(256) void conv_w(const float* __restrict__ W)
{
    __half* out = (N == 3072) ? g_wqf : g_wpf;
    __shared__ float t[32][33];
    const int k0 = blockIdx.x * 32, n0 = blockIdx.y * 32;
    const int tx = threadIdx.x, ty = threadIdx.y;      // 32 x 8
    #pragma unroll
    for (int i = 0; i < 4; i++)
        t[ty + 8*i][tx] = W[(size_t)(k0 + ty + 8*i) * N + n0 + tx];
    __syncthreads();
    #pragma unroll
    for (int i = 0; i < 4; i++) {
        float v = t[tx][ty + 8*i];
        __half h, l; hsplit(v, h, l);
        size_t o = (size_t)(n0 + ty + 8*i) * KDIM + k0 + tx;
        out[o] = h;
        out[(size_t)N * KDIM + o] = l;
    }
}

#define PLANE_BYTES 10240          // 128 rows * 80 B (32 elems*2B + 16B pad)
#define GEMM_STAGE (3*PLANE_BYTES)
#define GEMM_SMEM  (2*GEMM_STAGE)  // 61440

// ---------------------------------------------------------------------------
// 2-term fp16 GEMM core:  C[128x128 tile] = A @ B^T (+bias in epilogue)
// 256 threads, 8 warps, warp tile 32x64, dbl-buffered BK=32.
// MODE 0: A=g_xf, B=g_wqf (N=3072) -> q fp16, k/v fp16 hi+lo [B,H,T,D]
// MODE 1: A=g_yf, B=g_wpf (N=1024) -> Out fp32 [B,T,C]
// ---------------------------------------------------------------------------
template<int MODE>
__global__ __launch_bounds__(256, 2)
void gemm_f16_kernel(const float* __restrict__ bias, float* __restrict__ Out)
{
    extern __shared__ __align__(128) char smem[];
    constexpr int NT = MODE ? 1024 : 3072;
    const __half* __restrict__ Ap = MODE ? g_yf : g_xf;
    const __half* __restrict__ Bp = MODE ? g_wpf : g_wqf;
    constexpr size_t BPL = (size_t)NT * KDIM;

    const int tid  = threadIdx.x;
    const int lane = tid & 31, wid = tid >> 5;
    const int row0 = blockIdx.y * 128, col0 = blockIdx.x * 128;
    const int m0w  = (wid >> 1) * 32;
    const int n0w  = (wid & 1) * 64;
    const uint32_t sb = smem_to_u32(smem);

    float acc[2][8][4];
    #pragma unroll
    for (int a = 0; a < 2; a++)
        #pragma unroll
        for (int b = 0; b < 8; b++)
            #pragma unroll
            for (int c = 0; c < 4; c++) acc[a][b][c] = 0.f;

    auto issue = [&](int st, int ck) {
        const int k0 = ck * 32;
        const uint32_t s0 = sb + st * GEMM_STAGE;
        #pragma unroll
        for (int i = 0; i < 2; i++) {
            const int c = tid + i * 256;       // 512 16B chunks per plane
            const int r = c >> 2, kc = c & 3;
            const uint32_t so = r * 80 + kc * 16;
            cp16(s0 + so, Ap + (size_t)(row0 + r) * KDIM + k0 + kc * 8);
            const __half* gb = Bp + (size_t)(col0 + r) * KDIM + k0 + kc * 8;
            cp16(s0 + PLANE_BYTES   + so, gb);        // Bh
            cp16(s0 + 2*PLANE_BYTES + so, gb + BPL);  // Bl
        }
        asm volatile("cp.async.commit_group;" ::: "memory");
    };

    auto compute = [&](int st) {
        const uint32_t s0 = sb + st * GEMM_STAGE;
        const uint32_t rsel = (lane & 15);
        #pragma unroll
        for (int ks = 0; ks < 32; ks += 16) {
            const uint32_t coff = ks * 2 + 16 * (lane >> 4);
            uint32_t af[2][4];
            #pragma unroll
            for (int mt = 0; mt < 2; mt++)
                ldm_x4(af[mt], s0 + (m0w + mt*16 + rsel) * 80 + coff);
            #pragma unroll
            for (int nt = 0; nt < 4; nt++) {
                const uint32_t rb = s0 + PLANE_BYTES + (n0w + nt*16 + rsel) * 80 + coff;
                uint32_t bh[4], bl[4];
                ldm_x4(bh, rb);
                ldm_x4(bl, rb + PLANE_BYTES);
                #pragma unroll
                for (int mt = 0; mt < 2; mt++) {
                    mma_f16(acc[mt][nt*2],   af[mt], bh[0], bh[2]);
                    mma_f16(acc[mt][nt*2+1], af[mt], bh[1], bh[3]);
                    mma_f16(acc[mt][nt*2],   af[mt], bl[0], bl[2]);
                    mma_f16(acc[mt][nt*2+1], af[mt], bl[1], bl[3]);
                }
            }
        }
    };

    issue(0, 0);
    for (int ck = 0; ck < 32; ck++) {
        if (ck + 1 < 32) {
            issue((ck + 1) & 1, ck + 1);
            asm volatile("cp.async.wait_group 1;" ::: "memory");
        } else {
            asm volatile("cp.async.wait_group 0;" ::: "memory");
        }
        __syncthreads();
        compute(ck & 1);
        __syncthreads();
    }

    // ---- epilogue ----
    const int g   = lane >> 2;
    const int cql = (lane & 3) * 2;
    #pragma unroll
    for (int mt = 0; mt < 2; mt++) {
        #pragma unroll
        for (int nt = 0; nt < 8; nt++) {
            const int cg = col0 + n0w + nt * 8 + cql;
            const float b0 = bias[cg], b1 = bias[cg + 1];
            const int r0 = row0 + m0w + mt * 16 + g;
            if (MODE == 0) {
                const int which = cg >> 10;
                const int rem = cg & (CC - 1);
                const int h = rem >> 6, d0 = rem & (DH - 1);
                #pragma unroll
                for (int hf = 0; hf < 2; hf++) {
                    const float vx = acc[mt][nt][hf*2]   + b0;
                    const float vy = acc[mt][nt][hf*2+1] + b1;
                    const int rr = r0 + hf * 8;
                    const int bb = rr >> 11, t = rr & (TT - 1);
                    const size_t off = (((size_t)(bb*NH + h)*TT + t)*DH + d0) >> 1;
                    const uint32_t hw = pack_hf(vx, vy);
                    if (which == 0) {
                        ((uint32_t*)g_qf)[off] = hw;
                    } else {
                        __half2 hh = *(__half2*)&hw;
                        const uint32_t lw = pack_hf(vx - __half2float(hh.x),
                                                    vy - __half2float(hh.y));
                        uint32_t* ph = (which == 1) ? (uint32_t*)g_kf : (uint32_t*)g_vh;
                        uint32_t* pl = (which == 1) ? (uint32_t*)g_kl : (uint32_t*)g_vl;
                        ph[off] = hw;
                        pl[off] = lw;
                    }
                }
            } else {
                *(float2*)(Out + (size_t)r0 * CC + cg) =
                    make_float2(acc[mt][nt][0] + b0, acc[mt][nt][1] + b1);
                *(float2*)(Out + (size_t)(r0 + 8) * CC + cg) =
                    make_float2(acc[mt][nt][2] + b0, acc[mt][nt][3] + b1);
            }
        }
    }
}

// ---------------------------------------------------------------------------
// Flash attention on mma.sync, fp16 everywhere.
// Br=128 (8 warps x m16), Bc=64. QK^T: Q 1 plane x K hi+lo. PV: P x V hi+lo.
// Per-warp early-out on fully-masked diagonal sub-tiles.
// Epilogue writes y directly as fp16 (g_yf) for the fp16 proj GEMM.
// ---------------------------------------------------------------------------
#define QPL  9216                    // 64 * 144   (KV plane)
#define QPL2 18432                   // 128 * 144  (Q plane)
#define FL_STAGE (4*QPL)
#define FL_SMEM_BYTES (QPL2 + 2*FL_STAGE)   // 92160

__global__ __launch_bounds__(256)
void flash_mma_kernel()
{
    extern __shared__ __align__(128) char smem[];
    const uint32_t sb = smem_to_u32(smem);
    const int tid = threadIdx.x, lane = tid & 31, wid = tid >> 5;
    const int qt = (int)gridDim.x - 1 - (int)blockIdx.x;   // heavy tiles first
    const int bh = blockIdx.y;
    const size_t base = (size_t)bh * TT * DH;
    const int jmax = 2*qt + 1;

    // Q plane (128 rows) -> smem, part of cp.async group 0
    {
        const __half* q0 = g_qf + base + (size_t)qt * 128 * DH;
        #pragma unroll
        for (int i = 0; i < 4; i++) {
            const int ch = tid + i * 256;        // 1024 chunks
            const int r = ch >> 3, c = ch & 7;
            cp16(sb + r*144 + c*16, q0 + r*DH + c*8);
        }
    }
    const __half* kh = g_kf + base;
    const __half* kl = g_kl + base;
    const __half* vh = g_vh + base;
    const __half* vl = g_vl + base;

    auto issue_kv = [&](int jc, int st) {
        const uint32_t d0 = sb + QPL2 + st*FL_STAGE;
        const size_t g0 = (size_t)jc * 64 * DH;
        #pragma unroll
        for (int i = 0; i < 2; i++) {
            const int ch = tid + i * 256;        // 512 chunks per plane
            const int r = ch >> 3, c = ch & 7;
            const uint32_t so = r*144 + c*16;
            const size_t go = g0 + (size_t)r*DH + c*8;
            cp16(d0 +         so, kh + go);
            cp16(d0 +   QPL + so, kl + go);
            cp16(d0 + 2*QPL + so, vh + go);
            cp16(d0 + 3*QPL + so, vl + go);
        }
        asm volatile("cp.async.commit_group;" ::: "memory");
    };

    issue_kv(0, 0);   // group 0 (includes Q)

    uint32_t qf[4][4];
    float oacc[8][4];
    #pragma unroll
    for (int nt = 0; nt < 8; nt++)
        #pragma unroll
        for (int e = 0; e < 4; e++) oacc[nt][e] = 0.f;
    float m0 = -INFINITY, m1 = -INFINITY, l0 = 0.f, l1 = 0.f;

    const int rsel = lane & 15;
    const uint32_t chalf = 16 * (lane >> 4);
    const int vrow = (lane & 7) + 8 * ((lane >> 4) & 1);
    const uint32_t vcol = 16 * ((lane >> 3) & 1);
    const int wrow_max = qt*128 + wid*16 + 15;   // warp's max global q-row

    for (int jc = 0; jc <= jmax; jc++) {
        if (jc < jmax) {
            issue_kv(jc + 1, (jc + 1) & 1);
            asm volatile("cp.async.wait_group 1;" ::: "memory");
        } else {
            asm volatile("cp.async.wait_group 0;" ::: "memory");
        }
        __syncthreads();

        if (jc == 0) {   // Q fragments once (warp wid owns rows wid*16..+15)
            #pragma unroll
            for (int ku = 0; ku < 4; ku++)
                ldm_x4(qf[ku], sb + (uint32_t)((wid << 4) + rsel)*144 + ku*32 + chalf);
        }

        // fully-masked diagonal sub-tile for this warp -> skip body
        if (jc*64 <= wrow_max) {
            const uint32_t s0 = sb + QPL2 + (jc & 1)*FL_STAGE;

            // ---- S = Q @ K^T (2-term fp16) ----
            float s[8][4];
            #pragma unroll
            for (int nt = 0; nt < 8; nt++)
                #pragma unroll
                for (int e = 0; e < 4; e++) s[nt][e] = 0.f;

            #pragma unroll
            for (int ku = 0; ku < 4; ku++) {
                #pragma unroll
                for (int ng = 0; ng < 4; ng++) {
                    uint32_t kh4[4], kl4[4];
                    const uint32_t ka = s0 + (uint32_t)(ng*16 + rsel)*144 + ku*32 + chalf;
                    ldm_x4(kh4, ka);
                    ldm_x4(kl4, ka + QPL);
                    mma_f16(s[ng*2],   qf[ku], kh4[0], kh4[2]);
                    mma_f16(s[ng*2+1], qf[ku], kh4[1], kh4[3]);
                    mma_f16(s[ng*2],   qf[ku], kl4[0], kl4[2]);
                    mma_f16(s[ng*2+1], qf[ku], kl4[1], kl4[3]);
                }
            }

            // ---- scale + causal mask (last two KV tiles only) ----
            #pragma unroll
            for (int nt = 0; nt < 8; nt++)
                #pragma unroll
                for (int e = 0; e < 4; e++) s[nt][e] *= 0.125f;
            if (jc >= 2*qt) {
                const int r0l = qt*128 + wid*16 + (lane >> 2);
                const int cbb = jc*64 + (lane & 3) * 2;
                #pragma unroll
                for (int nt = 0; nt < 8; nt++) {
                    const int c0 = cbb + nt*8;
                    if (c0     > r0l    ) s[nt][0] = -INFINITY;
                    if (c0 + 1 > r0l    ) s[nt][1] = -INFINITY;
                    if (c0     > r0l + 8) s[nt][2] = -INFINITY;
                    if (c0 + 1 > r0l + 8) s[nt][3] = -INFINITY;
                }
            }

            // ---- online softmax (rows g and g+8; row on 4 lanes) ----
            float mx0 = -INFINITY, mx1 = -INFINITY;
            #pragma unroll
            for (int nt = 0; nt < 8; nt++) {
                mx0 = fmaxf(mx0, fmaxf(s[nt][0], s[nt][1]));
                mx1 = fmaxf(mx1, fmaxf(s[nt][2], s[nt][3]));
            }
            mx0 = fmaxf(mx0, __shfl_xor_sync(0xffffffffu, mx0, 1));
            mx0 = fmaxf(mx0, __shfl_xor_sync(0xffffffffu, mx0, 2));
            mx1 = fmaxf(mx1, __shfl_xor_sync(0xffffffffu, mx1, 1));
            mx1 = fmaxf(mx1, __shfl_xor_sync(0xffffffffu, mx1, 2));
            const float mn0 = fmaxf(m0, mx0), mn1 = fmaxf(m1, mx1);
            const float a0 = __expf(m0 - mn0), a1 = __expf(m1 - mn1);
            float sum0 = 0.f, sum1 = 0.f;
            #pragma unroll
            for (int nt = 0; nt < 8; nt++) {
                s[nt][0] = __expf(s[nt][0] - mn0); sum0 += s[nt][0];
                s[nt][1] = __expf(s[nt][1] - mn0); sum0 += s[nt][1];
                s[nt][2] = __expf(s[nt][2] - mn1); sum1 += s[nt][2];
                s[nt][3] = __expf(s[nt][3] - mn1); sum1 += s[nt][3];
            }
            sum0 += __shfl_xor_sync(0xffffffffu, sum0, 1);
            sum0 += __shfl_xor_sync(0xffffffffu, sum0, 2);
            sum1 += __shfl_xor_sync(0xffffffffu, sum1, 1);
            sum1 += __shfl_xor_sync(0xffffffffu, sum1, 2);
            l0 = l0 * a0 + sum0;  m0 = mn0;
            l1 = l1 * a1 + sum1;  m1 = mn1;
            #pragma unroll
            for (int nt = 0; nt < 8; nt++) {
                oacc[nt][0] *= a0; oacc[nt][1] *= a0;
                oacc[nt][2] *= a1; oacc[nt][3] *= a1;
            }

            // ---- O += P @ V (fp16 P, 2-term fp16 V) ----
            #pragma unroll
            for (int u = 0; u < 4; u++) {
                uint32_t pa[4];
                #pragma unroll
                for (int t = 0; t < 4; t++) {
                    const int j = 2*u + (t >> 1);
                    const int e0 = (t & 1) * 2;
                    pa[t] = pack_hf(s[j][e0], s[j][e0 + 1]);
                }
                #pragma unroll
                for (int dg = 0; dg < 4; dg++) {
                    uint32_t vh4[4], vl4[4];
                    const uint32_t va = s0 + 2*QPL + (uint32_t)(u*16 + vrow)*144 + dg*32 + vcol;
                    ldm_x4_t(vh4, va);
                    ldm_x4_t(vl4, va + QPL);
                    mma_f16(oacc[dg*2],   pa, vh4[0], vh4[2]);
                    mma_f16(oacc[dg*2+1], pa, vh4[1], vh4[3]);
                    mma_f16(oacc[dg*2],   pa, vl4[0], vl4[2]);
                    mma_f16(oacc[dg*2+1], pa, vl4[1], vl4[3]);
                }
            }
        }
        __syncthreads();   // stage reads done before refill
    }

    // ---- normalize + write y [B,T,C] as fp16 (feeds fp16 proj GEMM) ----
    const int g  = lane >> 2;
    const int t2 = (lane & 3) * 2;
    const int bb = bh >> 4, hh = bh & (NH - 1);
    const int row0 = qt*128 + (wid << 4) + g;
    const float inv0 = 1.0f / l0, inv1 = 1.0f / l1;
    uint32_t* y0 = (uint32_t*)(g_yf + ((size_t)bb*TT + row0)*CC + hh*DH);
    uint32_t* y1 = (uint32_t*)(g_yf + ((size_t)bb*TT + row0 + 8)*CC + hh*DH);
    #pragma unroll
    for (int nt = 0; nt < 8; nt++) {
        y0[(nt*8 + t2) >> 1] = pack_hf(oacc[nt][0]*inv0, oacc[nt][1]*inv0);
        y1[(nt*8 + t2) >> 1] = pack_hf(oacc[nt][2]*inv1, oacc[nt][3]*inv1);
    }
}

// ---------------------------------------------------------------------------
extern "C" void kernel_launch(void* const* d_in, const int* in_sizes, int n_in,
                              void* d_out, int out_size)
{
    (void)in_sizes; (void)n_in; (void)out_size;
    const float* x     = (const float*)d_in[0];
    const float* Wqkv  = (const float*)d_in[1];
    const float* bqkv  = (const float*)d_in[2];
    const float* Wproj = (const float*)d_in[3];
    const float* bproj = (const float*)d_in[4];
    float* out = (float*)d_out;

    static bool attr_set = false;
    if (!attr_set) {
        cudaFuncSetAttribute(flash_mma_kernel,
            cudaFuncAttributeMaxDynamicSharedMemorySize, FL_SMEM_BYTES);
        cudaFuncSetAttribute(gemm_f16_kernel<0>,
            cudaFuncAttributeMaxDynamicSharedMemorySize, GEMM_SMEM);
        cudaFuncSetAttribute(gemm_f16_kernel<1>,
            cudaFuncAttributeMaxDynamicSharedMemorySize, GEMM_SMEM);
        attr_set = true;
    }

    const int act4 = (MROWS * KDIM) / 4;

    // 0) conversions
    conv_x<<<act4 / 256, 256>>>(x);
    conv_w<3072><<<dim3(KDIM/32, 3072/32), dim3(32, 8)>>>(Wqkv);
    conv_w<1024><<<dim3(KDIM/32, 1024/32), dim3(32, 8)>>>(Wproj);

    // 1) QKV projection (fp16 2-term) -> q fp16, k/v fp16 hi+lo [B,H,T,D]
    gemm_f16_kernel<0><<<dim3(3072/128, MROWS/128), 256, GEMM_SMEM>>>(bqkv, nullptr);

    // 2) causal flash attention (Br=128) -> g_yf fp16 [B,T,C]
    flash_mma_kernel<<<dim3(TT/128, NB*NH), 256, FL_SMEM_BYTES>>>();

    // 3) output projection (fp16 2-term) -> d_out
    gemm_f16_kernel<1><<<dim3(1024/128, MROWS/128), 256, GEMM_SMEM>>>(bproj, out);
}

// round 14
// speedup vs baseline: 2.0750x; 1.4355x over previous
#include <cuda_runtime.h>
#include <cuda_bf16.h>
#include <cuda_fp16.h>
#include <math.h>
#include <stdint.h>

#define NB 4
#define NH 16
#define TT 2048
#define DH 64
#define CC 1024
#define MROWS (NB*TT)   // 8192
#define KDIM  1024

// ---------------------------------------------------------------------------
// Scratch (__device__ globals; allocation-free rule)
// ---------------------------------------------------------------------------
// q, k: single fp16 planes; v: fp16 hi+lo; all [B,H,T,D]
__device__ __half g_qf[NB*NH*TT*DH];
__device__ __half g_kf[NB*NH*TT*DH];
__device__ __half g_vh[NB*NH*TT*DH];
__device__ __half g_vl[NB*NH*TT*DH];

// y (attention out) single fp16 plane [B,T,C], written by flash epilogue
__device__ __half g_yf[(size_t)MROWS*KDIM];

// GEMM inputs: single fp16 planes
__device__ __half g_xf[(size_t)MROWS*KDIM];      // x
__device__ __half g_wqf[(size_t)3072*KDIM];      // Wqkv^T [3072][K]
__device__ __half g_wpf[(size_t)1024*KDIM];      // Wproj^T [1024][K]

// ---------------------------------------------------------------------------
// PTX helpers — compute_80-era ops only (harness PTX target lacks 'a' features)
// ---------------------------------------------------------------------------
__device__ __forceinline__ uint32_t smem_to_u32(const void* p) {
    uint32_t a;
    asm("{ .reg .u64 t; cvta.to.shared.u64 t, %1; cvt.u32.u64 %0, t; }"
        : "=r"(a) : "l"(p));
    return a;
}
__device__ __forceinline__ void cp16(uint32_t saddr, const void* g) {
    asm volatile("cp.async.cg.shared.global [%0], [%1], 16;"
                 :: "r"(saddr), "l"(g) : "memory");
}
__device__ __forceinline__ void ldm_x4(uint32_t (&r)[4], uint32_t addr) {
    asm volatile("ldmatrix.sync.aligned.m8n8.x4.shared.b16 {%0,%1,%2,%3}, [%4];"
        : "=r"(r[0]), "=r"(r[1]), "=r"(r[2]), "=r"(r[3]) : "r"(addr));
}
__device__ __forceinline__ void ldm_x4_t(uint32_t (&r)[4], uint32_t addr) {
    asm volatile("ldmatrix.sync.aligned.m8n8.x4.trans.shared.b16 {%0,%1,%2,%3}, [%4];"
        : "=r"(r[0]), "=r"(r[1]), "=r"(r[2]), "=r"(r[3]) : "r"(addr));
}
__device__ __forceinline__ void mma_f16(float (&d)[4], const uint32_t (&a)[4],
                                        uint32_t b0, uint32_t b1) {
    asm volatile("mma.sync.aligned.m16n8k16.row.col.f32.f16.f16.f32 "
        "{%0,%1,%2,%3}, {%4,%5,%6,%7}, {%8,%9}, {%0,%1,%2,%3};"
        : "+f"(d[0]), "+f"(d[1]), "+f"(d[2]), "+f"(d[3])
        : "r"(a[0]), "r"(a[1]), "r"(a[2]), "r"(a[3]), "r"(b0), "r"(b1));
}
// pack two fp32 into f16x2 word: low half = lo_elem
__device__ __forceinline__ uint32_t pack_hf(float lo_elem, float hi_elem) {
    __half2 h = __floats2half2_rn(lo_elem, hi_elem);
    return *(uint32_t*)&h;
}

// ---------------------------------------------------------------------------
// Conversion kernels
// ---------------------------------------------------------------------------
// x -> g_xf (single fp16 plane)
__global__ __launch_bounds__(256) void conv_x(const float* __restrict__ in)
{
    const size_t i = (size_t)blockIdx.x * 256 + threadIdx.x;   // per float4
    float4 v = ((const float4*)in)[i];
    __half h[4];
    h[0] = __float2half_rn(v.x); h[1] = __float2half_rn(v.y);
    h[2] = __float2half_rn(v.z); h[3] = __float2half_rn(v.w);
    *(uint2*)(g_xf + 4*i) = *(uint2*)h;
}

// W [K][N] -> out [N][K] (single fp16 plane, transposed)
template<int N>
__global__ __launch_bounds__(256) void conv_w(const float* __restrict__ W)
{
    __half* out = (N == 3072) ? g_wqf : g_wpf;
    __shared__ float t[32][33];
    const int k0 = blockIdx.x * 32, n0 = blockIdx.y * 32;
    const int tx = threadIdx.x, ty = threadIdx.y;      // 32 x 8
    #pragma unroll
    for (int i = 0; i < 4; i++)
        t[ty + 8*i][tx] = W[(size_t)(k0 + ty + 8*i) * N + n0 + tx];
    __syncthreads();
    #pragma unroll
    for (int i = 0; i < 4; i++)
        out[(size_t)(n0 + ty + 8*i) * KDIM + k0 + tx] =
            __float2half_rn(t[tx][ty + 8*i]);
}

#define PLANE_BYTES 10240          // 128 rows * 80 B (32 elems*2B + 16B pad)
#define GEMM_STAGE (2*PLANE_BYTES)
#define GEMM_SMEM  (2*GEMM_STAGE)  // 40960

// ---------------------------------------------------------------------------
// Single-term fp16 GEMM core:  C[128x128 tile] = A @ B^T (+bias in epilogue)
// 256 threads, 8 warps, warp tile 32x64, dbl-buffered BK=32.
// MODE 0: A=g_xf, B=g_wqf (N=3072) -> q,k fp16, v fp16 hi+lo [B,H,T,D]
// MODE 1: A=g_yf, B=g_wpf (N=1024) -> Out fp32 [B,T,C]
// ---------------------------------------------------------------------------
template<int MODE>
__global__ __launch_bounds__(256, 2)
void gemm_f16_kernel(const float* __restrict__ bias, float* __restrict__ Out)
{
    extern __shared__ __align__(128) char smem[];
    const __half* __restrict__ Ap = MODE ? g_yf : g_xf;
    const __half* __restrict__ Bp = MODE ? g_wpf : g_wqf;

    const int tid  = threadIdx.x;
    const int lane = tid & 31, wid = tid >> 5;
    const int row0 = blockIdx.y * 128, col0 = blockIdx.x * 128;
    const int m0w  = (wid >> 1) * 32;
    const int n0w  = (wid & 1) * 64;
    const uint32_t sb = smem_to_u32(smem);

    float acc[2][8][4];
    #pragma unroll
    for (int a = 0; a < 2; a++)
        #pragma unroll
        for (int b = 0; b < 8; b++)
            #pragma unroll
            for (int c = 0; c < 4; c++) acc[a][b][c] = 0.f;

    auto issue = [&](int st, int ck) {
        const int k0 = ck * 32;
        const uint32_t s0 = sb + st * GEMM_STAGE;
        #pragma unroll
        for (int i = 0; i < 2; i++) {
            const int c = tid + i * 256;       // 512 16B chunks per plane
            const int r = c >> 2, kc = c & 3;
            const uint32_t so = r * 80 + kc * 16;
            cp16(s0 + so, Ap + (size_t)(row0 + r) * KDIM + k0 + kc * 8);
            cp16(s0 + PLANE_BYTES + so,
                 Bp + (size_t)(col0 + r) * KDIM + k0 + kc * 8);
        }
        asm volatile("cp.async.commit_group;" ::: "memory");
    };

    auto compute = [&](int st) {
        const uint32_t s0 = sb + st * GEMM_STAGE;
        const uint32_t rsel = (lane & 15);
        #pragma unroll
        for (int ks = 0; ks < 32; ks += 16) {
            const uint32_t coff = ks * 2 + 16 * (lane >> 4);
            uint32_t af[2][4];
            #pragma unroll
            for (int mt = 0; mt < 2; mt++)
                ldm_x4(af[mt], s0 + (m0w + mt*16 + rsel) * 80 + coff);
            #pragma unroll
            for (int nt = 0; nt < 4; nt++) {
                uint32_t bh[4];
                ldm_x4(bh, s0 + PLANE_BYTES + (n0w + nt*16 + rsel) * 80 + coff);
                #pragma unroll
                for (int mt = 0; mt < 2; mt++) {
                    mma_f16(acc[mt][nt*2],   af[mt], bh[0], bh[2]);
                    mma_f16(acc[mt][nt*2+1], af[mt], bh[1], bh[3]);
                }
            }
        }
    };

    issue(0, 0);
    for (int ck = 0; ck < 32; ck++) {
        if (ck + 1 < 32) {
            issue((ck + 1) & 1, ck + 1);
            asm volatile("cp.async.wait_group 1;" ::: "memory");
        } else {
            asm volatile("cp.async.wait_group 0;" ::: "memory");
        }
        __syncthreads();
        compute(ck & 1);
        __syncthreads();
    }

    // ---- epilogue ----
    const int g   = lane >> 2;
    const int cql = (lane & 3) * 2;
    #pragma unroll
    for (int mt = 0; mt < 2; mt++) {
        #pragma unroll
        for (int nt = 0; nt < 8; nt++) {
            const int cg = col0 + n0w + nt * 8 + cql;
            const float b0 = bias[cg], b1 = bias[cg + 1];
            const int r0 = row0 + m0w + mt * 16 + g;
            if (MODE == 0) {
                const int which = cg >> 10;
                const int rem = cg & (CC - 1);
                const int h = rem >> 6, d0 = rem & (DH - 1);
                #pragma unroll
                for (int hf = 0; hf < 2; hf++) {
                    const float vx = acc[mt][nt][hf*2]   + b0;
                    const float vy = acc[mt][nt][hf*2+1] + b1;
                    const int rr = r0 + hf * 8;
                    const int bb = rr >> 11, t = rr & (TT - 1);
                    const size_t off = (((size_t)(bb*NH + h)*TT + t)*DH + d0) >> 1;
                    const uint32_t hw = pack_hf(vx, vy);
                    if (which == 0) {
                        ((uint32_t*)g_qf)[off] = hw;
                    } else if (which == 1) {
                        ((uint32_t*)g_kf)[off] = hw;
                    } else {
                        __half2 hh = *(__half2*)&hw;
                        const uint32_t lw = pack_hf(vx - __half2float(hh.x),
                                                    vy - __half2float(hh.y));
                        ((uint32_t*)g_vh)[off] = hw;
                        ((uint32_t*)g_vl)[off] = lw;
                    }
                }
            } else {
                *(float2*)(Out + (size_t)r0 * CC + cg) =
                    make_float2(acc[mt][nt][0] + b0, acc[mt][nt][1] + b1);
                *(float2*)(Out + (size_t)(r0 + 8) * CC + cg) =
                    make_float2(acc[mt][nt][2] + b0, acc[mt][nt][3] + b1);
            }
        }
    }
}

// ---------------------------------------------------------------------------
// Flash attention on mma.sync, fp16.
// Br=128 (8 warps x m16), Bc=64. QK^T: Q x K single planes. PV: P x V hi+lo.
// Per-warp early-out on fully-masked diagonal sub-tiles.
// Epilogue writes y directly as fp16 (g_yf) for the fp16 proj GEMM.
// ---------------------------------------------------------------------------
#define QPL  9216                    // 64 * 144   (KV plane)
#define QPL2 18432                   // 128 * 144  (Q plane)
#define FL_STAGE (3*QPL)             // Kh, Vh, Vl
#define FL_SMEM_BYTES (QPL2 + 2*FL_STAGE)   // 73728

__global__ __launch_bounds__(256)
void flash_mma_kernel()
{
    extern __shared__ __align__(128) char smem[];
    const uint32_t sb = smem_to_u32(smem);
    const int tid = threadIdx.x, lane = tid & 31, wid = tid >> 5;
    const int qt = (int)gridDim.x - 1 - (int)blockIdx.x;   // heavy tiles first
    const int bh = blockIdx.y;
    const size_t base = (size_t)bh * TT * DH;
    const int jmax = 2*qt + 1;

    // Q plane (128 rows) -> smem, part of cp.async group 0
    {
        const __half* q0 = g_qf + base + (size_t)qt * 128 * DH;
        #pragma unroll
        for (int i = 0; i < 4; i++) {
            const int ch = tid + i * 256;        // 1024 chunks
            const int r = ch >> 3, c = ch & 7;
            cp16(sb + r*144 + c*16, q0 + r*DH + c*8);
        }
    }
    const __half* kh = g_kf + base;
    const __half* vh = g_vh + base;
    const __half* vl = g_vl + base;

    auto issue_kv = [&](int jc, int st) {
        const uint32_t d0 = sb + QPL2 + st*FL_STAGE;
        const size_t g0 = (size_t)jc * 64 * DH;
        #pragma unroll
        for (int i = 0; i < 2; i++) {
            const int ch = tid + i * 256;        // 512 chunks per plane
            const int r = ch >> 3, c = ch & 7;
            const uint32_t so = r*144 + c*16;
            const size_t go = g0 + (size_t)r*DH + c*8;
            cp16(d0 +         so, kh + go);
            cp16(d0 +   QPL + so, vh + go);
            cp16(d0 + 2*QPL + so, vl + go);
        }
        asm volatile("cp.async.commit_group;" ::: "memory");
    };

    issue_kv(0, 0);   // group 0 (includes Q)

    uint32_t qf[4][4];
    float oacc[8][4];
    #pragma unroll
    for (int nt = 0; nt < 8; nt++)
        #pragma unroll
        for (int e = 0; e < 4; e++) oacc[nt][e] = 0.f;
    float m0 = -INFINITY, m1 = -INFINITY, l0 = 0.f, l1 = 0.f;

    const int rsel = lane & 15;
    const uint32_t chalf = 16 * (lane >> 4);
    const int vrow = (lane & 7) + 8 * ((lane >> 4) & 1);
    const uint32_t vcol = 16 * ((lane >> 3) & 1);
    const int wrow_max = qt*128 + wid*16 + 15;   // warp's max global q-row

    for (int jc = 0; jc <= jmax; jc++) {
        if (jc < jmax) {
            issue_kv(jc + 1, (jc + 1) & 1);
            asm volatile("cp.async.wait_group 1;" ::: "memory");
        } else {
            asm volatile("cp.async.wait_group 0;" ::: "memory");
        }
        __syncthreads();

        if (jc == 0) {   // Q fragments once (warp wid owns rows wid*16..+15)
            #pragma unroll
            for (int ku = 0; ku < 4; ku++)
                ldm_x4(qf[ku], sb + (uint32_t)((wid << 4) + rsel)*144 + ku*32 + chalf);
        }

        // fully-masked diagonal sub-tile for this warp -> skip body
        if (jc*64 <= wrow_max) {
            const uint32_t s0 = sb + QPL2 + (jc & 1)*FL_STAGE;

            // ---- S = Q @ K^T (single fp16) ----
            float s[8][4];
            #pragma unroll
            for (int nt = 0; nt < 8; nt++)
                #pragma unroll
                for (int e = 0; e < 4; e++) s[nt][e] = 0.f;

            #pragma unroll
            for (int ku = 0; ku < 4; ku++) {
                #pragma unroll
                for (int ng = 0; ng < 4; ng++) {
                    uint32_t kh4[4];
                    ldm_x4(kh4, s0 + (uint32_t)(ng*16 + rsel)*144 + ku*32 + chalf);
                    mma_f16(s[ng*2],   qf[ku], kh4[0], kh4[2]);
                    mma_f16(s[ng*2+1], qf[ku], kh4[1], kh4[3]);
                }
            }

            // ---- scale + causal mask (last two KV tiles only) ----
            #pragma unroll
            for (int nt = 0; nt < 8; nt++)
                #pragma unroll
                for (int e = 0; e < 4; e++) s[nt][e] *= 0.125f;
            if (jc >= 2*qt) {
                const int r0l = qt*128 + wid*16 + (lane >> 2);
                const int cbb = jc*64 + (lane & 3) * 2;
                #pragma unroll
                for (int nt = 0; nt < 8; nt++) {
                    const int c0 = cbb + nt*8;
                    if (c0     > r0l    ) s[nt][0] = -INFINITY;
                    if (c0 + 1 > r0l    ) s[nt][1] = -INFINITY;
                    if (c0     > r0l + 8) s[nt][2] = -INFINITY;
                    if (c0 + 1 > r0l + 8) s[nt][3] = -INFINITY;
                }
            }

            // ---- online softmax (rows g and g+8; row on 4 lanes) ----
            float mx0 = -INFINITY, mx1 = -INFINITY;
            #pragma unroll
            for (int nt = 0; nt < 8; nt++) {
                mx0 = fmaxf(mx0, fmaxf(s[nt][0], s[nt][1]));
                mx1 = fmaxf(mx1, fmaxf(s[nt][2], s[nt][3]));
            }
            mx0 = fmaxf(mx0, __shfl_xor_sync(0xffffffffu, mx0, 1));
            mx0 = fmaxf(mx0, __shfl_xor_sync(0xffffffffu, mx0, 2));
            mx1 = fmaxf(mx1, __shfl_xor_sync(0xffffffffu, mx1, 1));
            mx1 = fmaxf(mx1, __shfl_xor_sync(0xffffffffu, mx1, 2));
            const float mn0 = fmaxf(m0, mx0), mn1 = fmaxf(m1, mx1);
            const float a0 = __expf(m0 - mn0), a1 = __expf(m1 - mn1);
            float sum0 = 0.f, sum1 = 0.f;
            #pragma unroll
            for (int nt = 0; nt < 8; nt++) {
                s[nt][0] = __expf(s[nt][0] - mn0); sum0 += s[nt][0];
                s[nt][1] = __expf(s[nt][1] - mn0); sum0 += s[nt][1];
                s[nt][2] = __expf(s[nt][2] - mn1); sum1 += s[nt][2];
                s[nt][3] = __expf(s[nt][3] - mn1); sum1 += s[nt][3];
            }
            sum0 += __shfl_xor_sync(0xffffffffu, sum0, 1);
            sum0 += __shfl_xor_sync(0xffffffffu, sum0, 2);
            sum1 += __shfl_xor_sync(0xffffffffu, sum1, 1);
            sum1 += __shfl_xor_sync(0xffffffffu, sum1, 2);
            l0 = l0 * a0 + sum0;  m0 = mn0;
            l1 = l1 * a1 + sum1;  m1 = mn1;
            #pragma unroll
            for (int nt = 0; nt < 8; nt++) {
                oacc[nt][0] *= a0; oacc[nt][1] *= a0;
                oacc[nt][2] *= a1; oacc[nt][3] *= a1;
            }

            // ---- O += P @ V (fp16 P, 2-term fp16 V) ----
            #pragma unroll
            for (int u = 0; u < 4; u++) {
                uint32_t pa[4];
                #pragma unroll
                for (int t = 0; t < 4; t++) {
                    const int j = 2*u + (t >> 1);
                    const int e0 = (t & 1) * 2;
                    pa[t] = pack_hf(s[j][e0], s[j][e0 + 1]);
                }
                #pragma unroll
                for (int dg = 0; dg < 4; dg++) {
                    uint32_t vh4[4], vl4[4];
                    const uint32_t va = s0 + QPL + (uint32_t)(u*16 + vrow)*144 + dg*32 + vcol;
                    ldm_x4_t(vh4, va);
                    ldm_x4_t(vl4, va + QPL);
                    mma_f16(oacc[dg*2],   pa, vh4[0], vh4[2]);
                    mma_f16(oacc[dg*2+1], pa, vh4[1], vh4[3]);
                    mma_f16(oacc[dg*2],   pa, vl4[0], vl4[2]);
                    mma_f16(oacc[dg*2+1], pa, vl4[1], vl4[3]);
                }
            }
        }
        __syncthreads();   // stage reads done before refill
    }

    // ---- normalize + write y [B,T,C] as fp16 (feeds fp16 proj GEMM) ----
    const int g  = lane >> 2;
    const int t2 = (lane & 3) * 2;
    const int bb = bh >> 4, hh = bh & (NH - 1);
    const int row0 = qt*128 + (wid << 4) + g;
    const float inv0 = 1.0f / l0, inv1 = 1.0f / l1;
    uint32_t* y0 = (uint32_t*)(g_yf + ((size_t)bb*TT + row0)*CC + hh*DH);
    uint32_t* y1 = (uint32_t*)(g_yf + ((size_t)bb*TT + row0 + 8)*CC + hh*DH);
    #pragma unroll
    for (int nt = 0; nt < 8; nt++) {
        y0[(nt*8 + t2) >> 1] = pack_hf(oacc[nt][0]*inv0, oacc[nt][1]*inv0);
        y1[(nt*8 + t2) >> 1] = pack_hf(oacc[nt][2]*inv1, oacc[nt][3]*inv1);
    }
}

// ---------------------------------------------------------------------------
extern "C" void kernel_launch(void* const* d_in, const int* in_sizes, int n_in,
                              void* d_out, int out_size)
{
    (void)in_sizes; (void)n_in; (void)out_size;
    const float* x     = (const float*)d_in[0];
    const float* Wqkv  = (const float*)d_in[1];
    const float* bqkv  = (const float*)d_in[2];
    const float* Wproj = (const float*)d_in[3];
    const float* bproj = (const float*)d_in[4];
    float* out = (float*)d_out;

    static bool attr_set = false;
    if (!attr_set) {
        cudaFuncSetAttribute(flash_mma_kernel,
            cudaFuncAttributeMaxDynamicSharedMemorySize, FL_SMEM_BYTES);
        cudaFuncSetAttribute(gemm_f16_kernel<0>,
            cudaFuncAttributeMaxDynamicSharedMemorySize, GEMM_SMEM);
        cudaFuncSetAttribute(gemm_f16_kernel<1>,
            cudaFuncAttributeMaxDynamicSharedMemorySize, GEMM_SMEM);
        attr_set = true;
    }

    const int act4 = (MROWS * KDIM) / 4;

    // 0) conversions (all single fp16 planes)
    conv_x<<<act4 / 256, 256>>>(x);
    conv_w<3072><<<dim3(KDIM/32, 3072/32), dim3(32, 8)>>>(Wqkv);
    conv_w<1024><<<dim3(KDIM/32, 1024/32), dim3(32, 8)>>>(Wproj);

    // 1) QKV projection (single-term fp16) -> q,k fp16, v fp16 hi+lo
    gemm_f16_kernel<0><<<dim3(3072/128, MROWS/128), 256, GEMM_SMEM>>>(bqkv, nullptr);

    // 2) causal flash attention (Br=128) -> g_yf fp16 [B,T,C]
    flash_mma_kernel<<<dim3(TT/128, NB*NH), 256, FL_SMEM_BYTES>>>();

    // 3) output projection (single-term fp16) -> d_out
    gemm_f16_kernel<1><<<dim3(1024/128, MROWS/128), 256, GEMM_SMEM>>>(bproj, out);
}

// round 15
// speedup vs baseline: 2.3167x; 1.1165x over previous
#include <cuda_runtime.h>
#include <cuda_bf16.h>
#include <cuda_fp16.h>
#include <math.h>
#include <stdint.h>

#define NB 4
#define NH 16
#define TT 2048
#define DH 64
#define CC 1024
#define MROWS (NB*TT)   // 8192
#define KDIM  1024

// ---------------------------------------------------------------------------
// Scratch (__device__ globals; allocation-free rule)
// ---------------------------------------------------------------------------
// q, k, v: single fp16 planes [B,H,T,D]
__device__ __half g_qf[NB*NH*TT*DH];
__device__ __half g_kf[NB*NH*TT*DH];
__device__ __half g_vf[NB*NH*TT*DH];

// y (attention out) single fp16 plane [B,T,C], written by flash epilogue
__device__ __half g_yf[(size_t)MROWS*KDIM];

// GEMM inputs: single fp16 planes
__device__ __half g_xf[(size_t)MROWS*KDIM];      // x
__device__ __half g_wqf[(size_t)3072*KDIM];      // Wqkv^T [3072][K]
__device__ __half g_wpf[(size_t)1024*KDIM];      // Wproj^T [1024][K]

// ---------------------------------------------------------------------------
// PTX helpers — compute_80-era ops only (harness PTX target lacks 'a' features)
// ---------------------------------------------------------------------------
__device__ __forceinline__ uint32_t smem_to_u32(const void* p) {
    uint32_t a;
    asm("{ .reg .u64 t; cvta.to.shared.u64 t, %1; cvt.u32.u64 %0, t; }"
        : "=r"(a) : "l"(p));
    return a;
}
__device__ __forceinline__ void cp16(uint32_t saddr, const void* g) {
    asm volatile("cp.async.cg.shared.global [%0], [%1], 16;"
                 :: "r"(saddr), "l"(g) : "memory");
}
__device__ __forceinline__ void ldm_x4(uint32_t (&r)[4], uint32_t addr) {
    asm volatile("ldmatrix.sync.aligned.m8n8.x4.shared.b16 {%0,%1,%2,%3}, [%4];"
        : "=r"(r[0]), "=r"(r[1]), "=r"(r[2]), "=r"(r[3]) : "r"(addr));
}
__device__ __forceinline__ void ldm_x4_t(uint32_t (&r)[4], uint32_t addr) {
    asm volatile("ldmatrix.sync.aligned.m8n8.x4.trans.shared.b16 {%0,%1,%2,%3}, [%4];"
        : "=r"(r[0]), "=r"(r[1]), "=r"(r[2]), "=r"(r[3]) : "r"(addr));
}
__device__ __forceinline__ void mma_f16(float (&d)[4], const uint32_t (&a)[4],
                                        uint32_t b0, uint32_t b1) {
    asm volatile("mma.sync.aligned.m16n8k16.row.col.f32.f16.f16.f32 "
        "{%0,%1,%2,%3}, {%4,%5,%6,%7}, {%8,%9}, {%0,%1,%2,%3};"
        : "+f"(d[0]), "+f"(d[1]), "+f"(d[2]), "+f"(d[3])
        : "r"(a[0]), "r"(a[1]), "r"(a[2]), "r"(a[3]), "r"(b0), "r"(b1));
}
// pack two fp32 into f16x2 word: low half = lo_elem
__device__ __forceinline__ uint32_t pack_hf(float lo_elem, float hi_elem) {
    __half2 h = __floats2half2_rn(lo_elem, hi_elem);
    return *(uint32_t*)&h;
}

// ---------------------------------------------------------------------------
// Conversion kernels
// ---------------------------------------------------------------------------
// x -> g_xf (single fp16 plane)
__global__ __launch_bounds__(256) void conv_x(const float* __restrict__ in)
{
    const size_t i = (size_t)blockIdx.x * 256 + threadIdx.x;   // per float4
    float4 v = ((const float4*)in)[i];
    __half h[4];
    h[0] = __float2half_rn(v.x); h[1] = __float2half_rn(v.y);
    h[2] = __float2half_rn(v.z); h[3] = __float2half_rn(v.w);
    *(uint2*)(g_xf + 4*i) = *(uint2*)h;
}

// W [K][N] -> out [N][K] (single fp16 plane, transposed)
template<int N>
__global__ __launch_bounds__(256) void conv_w(const float* __restrict__ W)
{
    __half* out = (N == 3072) ? g_wqf : g_wpf;
    __shared__ float t[32][33];
    const int k0 = blockIdx.x * 32, n0 = blockIdx.y * 32;
    const int tx = threadIdx.x, ty = threadIdx.y;      // 32 x 8
    #pragma unroll
    for (int i = 0; i < 4; i++)
        t[ty + 8*i][tx] = W[(size_t)(k0 + ty + 8*i) * N + n0 + tx];
    __syncthreads();
    #pragma unroll
    for (int i = 0; i < 4; i++)
        out[(size_t)(n0 + ty + 8*i) * KDIM + k0 + tx] =
            __float2half_rn(t[tx][ty + 8*i]);
}

#define PLANE_BYTES 10240          // 128 rows * 80 B (32 elems*2B + 16B pad)
#define GEMM_STAGE (2*PLANE_BYTES)
#define GEMM_SMEM  (2*GEMM_STAGE)  // 40960

// ---------------------------------------------------------------------------
// Single-term fp16 GEMM core:  C[128x128 tile] = A @ B^T (+bias in epilogue)
// 256 threads, 8 warps, warp tile 32x64, dbl-buffered BK=32.
// MODE 0: A=g_xf, B=g_wqf (N=3072) -> q,k,v fp16 [B,H,T,D]
// MODE 1: A=g_yf, B=g_wpf (N=1024) -> Out fp32 [B,T,C]
// ---------------------------------------------------------------------------
template<int MODE>
__global__ __launch_bounds__(256, 2)
void gemm_f16_kernel(const float* __restrict__ bias, float* __restrict__ Out)
{
    extern __shared__ __align__(128) char smem[];
    const __half* __restrict__ Ap = MODE ? g_yf : g_xf;
    const __half* __restrict__ Bp = MODE ? g_wpf : g_wqf;

    const int tid  = threadIdx.x;
    const int lane = tid & 31, wid = tid >> 5;
    const int row0 = blockIdx.y * 128, col0 = blockIdx.x * 128;
    const int m0w  = (wid >> 1) * 32;
    const int n0w  = (wid & 1) * 64;
    const uint32_t sb = smem_to_u32(smem);

    float acc[2][8][4];
    #pragma unroll
    for (int a = 0; a < 2; a++)
        #pragma unroll
        for (int b = 0; b < 8; b++)
            #pragma unroll
            for (int c = 0; c < 4; c++) acc[a][b][c] = 0.f;

    auto issue = [&](int st, int ck) {
        const int k0 = ck * 32;
        const uint32_t s0 = sb + st * GEMM_STAGE;
        #pragma unroll
        for (int i = 0; i < 2; i++) {
            const int c = tid + i * 256;       // 512 16B chunks per plane
            const int r = c >> 2, kc = c & 3;
            const uint32_t so = r * 80 + kc * 16;
            cp16(s0 + so, Ap + (size_t)(row0 + r) * KDIM + k0 + kc * 8);
            cp16(s0 + PLANE_BYTES + so,
                 Bp + (size_t)(col0 + r) * KDIM + k0 + kc * 8);
        }
        asm volatile("cp.async.commit_group;" ::: "memory");
    };

    auto compute = [&](int st) {
        const uint32_t s0 = sb + st * GEMM_STAGE;
        const uint32_t rsel = (lane & 15);
        #pragma unroll
        for (int ks = 0; ks < 32; ks += 16) {
            const uint32_t coff = ks * 2 + 16 * (lane >> 4);
            uint32_t af[2][4];
            #pragma unroll
            for (int mt = 0; mt < 2; mt++)
                ldm_x4(af[mt], s0 + (m0w + mt*16 + rsel) * 80 + coff);
            #pragma unroll
            for (int nt = 0; nt < 4; nt++) {
                uint32_t bh[4];
                ldm_x4(bh, s0 + PLANE_BYTES + (n0w + nt*16 + rsel) * 80 + coff);
                #pragma unroll
                for (int mt = 0; mt < 2; mt++) {
                    mma_f16(acc[mt][nt*2],   af[mt], bh[0], bh[2]);
                    mma_f16(acc[mt][nt*2+1], af[mt], bh[1], bh[3]);
                }
            }
        }
    };

    issue(0, 0);
    for (int ck = 0; ck < 32; ck++) {
        if (ck + 1 < 32) {
            issue((ck + 1) & 1, ck + 1);
            asm volatile("cp.async.wait_group 1;" ::: "memory");
        } else {
            asm volatile("cp.async.wait_group 0;" ::: "memory");
        }
        __syncthreads();
        compute(ck & 1);
        __syncthreads();
    }

    // ---- epilogue ----
    const int g   = lane >> 2;
    const int cql = (lane & 3) * 2;
    #pragma unroll
    for (int mt = 0; mt < 2; mt++) {
        #pragma unroll
        for (int nt = 0; nt < 8; nt++) {
            const int cg = col0 + n0w + nt * 8 + cql;
            const float b0 = bias[cg], b1 = bias[cg + 1];
            const int r0 = row0 + m0w + mt * 16 + g;
            if (MODE == 0) {
                const int which = cg >> 10;
                const int rem = cg & (CC - 1);
                const int h = rem >> 6, d0 = rem & (DH - 1);
                uint32_t* dst = (which == 0) ? (uint32_t*)g_qf
                              : (which == 1) ? (uint32_t*)g_kf
                                             : (uint32_t*)g_vf;
                #pragma unroll
                for (int hf = 0; hf < 2; hf++) {
                    const float vx = acc[mt][nt][hf*2]   + b0;
                    const float vy = acc[mt][nt][hf*2+1] + b1;
                    const int rr = r0 + hf * 8;
                    const int bb = rr >> 11, t = rr & (TT - 1);
                    const size_t off = (((size_t)(bb*NH + h)*TT + t)*DH + d0) >> 1;
                    dst[off] = pack_hf(vx, vy);
                }
            } else {
                *(float2*)(Out + (size_t)r0 * CC + cg) =
                    make_float2(acc[mt][nt][0] + b0, acc[mt][nt][1] + b1);
                *(float2*)(Out + (size_t)(r0 + 8) * CC + cg) =
                    make_float2(acc[mt][nt][2] + b0, acc[mt][nt][3] + b1);
            }
        }
    }
}

// ---------------------------------------------------------------------------
// Flash attention on mma.sync, single fp16 planes throughout.
// Br=128 (8 warps x m16), Bc=64. QK^T: Q x K. PV: P x V.
// Per-warp early-out on fully-masked diagonal sub-tiles.
// Epilogue writes y directly as fp16 (g_yf) for the fp16 proj GEMM.
// ---------------------------------------------------------------------------
#define QPL  9216                    // 64 * 144   (KV plane)
#define QPL2 18432                   // 128 * 144  (Q plane)
#define FL_STAGE (2*QPL)             // K, V
#define FL_SMEM_BYTES (QPL2 + 2*FL_STAGE)   // 55296

__global__ __launch_bounds__(256)
void flash_mma_kernel()
{
    extern __shared__ __align__(128) char smem[];
    const uint32_t sb = smem_to_u32(smem);
    const int tid = threadIdx.x, lane = tid & 31, wid = tid >> 5;
    const int qt = (int)gridDim.x - 1 - (int)blockIdx.x;   // heavy tiles first
    const int bh = blockIdx.y;
    const size_t base = (size_t)bh * TT * DH;
    const int jmax = 2*qt + 1;

    // Q plane (128 rows) -> smem, part of cp.async group 0
    {
        const __half* q0 = g_qf + base + (size_t)qt * 128 * DH;
        #pragma unroll
        for (int i = 0; i < 4; i++) {
            const int ch = tid + i * 256;        // 1024 chunks
            const int r = ch >> 3, c = ch & 7;
            cp16(sb + r*144 + c*16, q0 + r*DH + c*8);
        }
    }
    const __half* kh = g_kf + base;
    const __half* vh = g_vf + base;

    auto issue_kv = [&](int jc, int st) {
        const uint32_t d0 = sb + QPL2 + st*FL_STAGE;
        const size_t g0 = (size_t)jc * 64 * DH;
        #pragma unroll
        for (int i = 0; i < 2; i++) {
            const int ch = tid + i * 256;        // 512 chunks per plane
            const int r = ch >> 3, c = ch & 7;
            const uint32_t so = r*144 + c*16;
            const size_t go = g0 + (size_t)r*DH + c*8;
            cp16(d0 +       so, kh + go);
            cp16(d0 + QPL + so, vh + go);
        }
        asm volatile("cp.async.commit_group;" ::: "memory");
    };

    issue_kv(0, 0);   // group 0 (includes Q)

    uint32_t qf[4][4];
    float oacc[8][4];
    #pragma unroll
    for (int nt = 0; nt < 8; nt++)
        #pragma unroll
        for (int e = 0; e < 4; e++) oacc[nt][e] = 0.f;
    float m0 = -INFINITY, m1 = -INFINITY, l0 = 0.f, l1 = 0.f;

    const int rsel = lane & 15;
    const uint32_t chalf = 16 * (lane >> 4);
    const int vrow = (lane & 7) + 8 * ((lane >> 4) & 1);
    const uint32_t vcol = 16 * ((lane >> 3) & 1);
    const int wrow_max = qt*128 + wid*16 + 15;   // warp's max global q-row

    for (int jc = 0; jc <= jmax; jc++) {
        if (jc < jmax) {
            issue_kv(jc + 1, (jc + 1) & 1);
            asm volatile("cp.async.wait_group 1;" ::: "memory");
        } else {
            asm volatile("cp.async.wait_group 0;" ::: "memory");
        }
        __syncthreads();

        if (jc == 0) {   // Q fragments once (warp wid owns rows wid*16..+15)
            #pragma unroll
            for (int ku = 0; ku < 4; ku++)
                ldm_x4(qf[ku], sb + (uint32_t)((wid << 4) + rsel)*144 + ku*32 + chalf);
        }

        // fully-masked diagonal sub-tile for this warp -> skip body
        if (jc*64 <= wrow_max) {
            const uint32_t s0 = sb + QPL2 + (jc & 1)*FL_STAGE;

            // ---- S = Q @ K^T (single fp16) ----
            float s[8][4];
            #pragma unroll
            for (int nt = 0; nt < 8; nt++)
                #pragma unroll
                for (int e = 0; e < 4; e++) s[nt][e] = 0.f;

            #pragma unroll
            for (int ku = 0; ku < 4; ku++) {
                #pragma unroll
                for (int ng = 0; ng < 4; ng++) {
                    uint32_t kh4[4];
                    ldm_x4(kh4, s0 + (uint32_t)(ng*16 + rsel)*144 + ku*32 + chalf);
                    mma_f16(s[ng*2],   qf[ku], kh4[0], kh4[2]);
                    mma_f16(s[ng*2+1], qf[ku], kh4[1], kh4[3]);
                }
            }

            // ---- scale + causal mask (last two KV tiles only) ----
            #pragma unroll
            for (int nt = 0; nt < 8; nt++)
                #pragma unroll
                for (int e = 0; e < 4; e++) s[nt][e] *= 0.125f;
            if (jc >= 2*qt) {
                const int r0l = qt*128 + wid*16 + (lane >> 2);
                const int cbb = jc*64 + (lane & 3) * 2;
                #pragma unroll
                for (int nt = 0; nt < 8; nt++) {
                    const int c0 = cbb + nt*8;
                    if (c0     > r0l    ) s[nt][0] = -INFINITY;
                    if (c0 + 1 > r0l    ) s[nt][1] = -INFINITY;
                    if (c0     > r0l + 8) s[nt][2] = -INFINITY;
                    if (c0 + 1 > r0l + 8) s[nt][3] = -INFINITY;
                }
            }

            // ---- online softmax (rows g and g+8; row on 4 lanes) ----
            float mx0 = -INFINITY, mx1 = -INFINITY;
            #pragma unroll
            for (int nt = 0; nt < 8; nt++) {
                mx0 = fmaxf(mx0, fmaxf(s[nt][0], s[nt][1]));
                mx1 = fmaxf(mx1, fmaxf(s[nt][2], s[nt][3]));
            }
            mx0 = fmaxf(mx0, __shfl_xor_sync(0xffffffffu, mx0, 1));
            mx0 = fmaxf(mx0, __shfl_xor_sync(0xffffffffu, mx0, 2));
            mx1 = fmaxf(mx1, __shfl_xor_sync(0xffffffffu, mx1, 1));
            mx1 = fmaxf(mx1, __shfl_xor_sync(0xffffffffu, mx1, 2));
            const float mn0 = fmaxf(m0, mx0), mn1 = fmaxf(m1, mx1);
            const float a0 = __expf(m0 - mn0), a1 = __expf(m1 - mn1);
            float sum0 = 0.f, sum1 = 0.f;
            #pragma unroll
            for (int nt = 0; nt < 8; nt++) {
                s[nt][0] = __expf(s[nt][0] - mn0); sum0 += s[nt][0];
                s[nt][1] = __expf(s[nt][1] - mn0); sum0 += s[nt][1];
                s[nt][2] = __expf(s[nt][2] - mn1); sum1 += s[nt][2];
                s[nt][3] = __expf(s[nt][3] - mn1); sum1 += s[nt][3];
            }
            sum0 += __shfl_xor_sync(0xffffffffu, sum0, 1);
            sum0 += __shfl_xor_sync(0xffffffffu, sum0, 2);
            sum1 += __shfl_xor_sync(0xffffffffu, sum1, 1);
            sum1 += __shfl_xor_sync(0xffffffffu, sum1, 2);
            l0 = l0 * a0 + sum0;  m0 = mn0;
            l1 = l1 * a1 + sum1;  m1 = mn1;
            #pragma unroll
            for (int nt = 0; nt < 8; nt++) {
                oacc[nt][0] *= a0; oacc[nt][1] *= a0;
                oacc[nt][2] *= a1; oacc[nt][3] *= a1;
            }

            // ---- O += P @ V (fp16 P, single fp16 V) ----
            #pragma unroll
            for (int u = 0; u < 4; u++) {
                uint32_t pa[4];
                #pragma unroll
                for (int t = 0; t < 4; t++) {
                    const int j = 2*u + (t >> 1);
                    const int e0 = (t & 1) * 2;
                    pa[t] = pack_hf(s[j][e0], s[j][e0 + 1]);
                }
                #pragma unroll
                for (int dg = 0; dg < 4; dg++) {
                    uint32_t vh4[4];
                    ldm_x4_t(vh4, s0 + QPL + (uint32_t)(u*16 + vrow)*144 + dg*32 + vcol);
                    mma_f16(oacc[dg*2],   pa, vh4[0], vh4[2]);
                    mma_f16(oacc[dg*2+1], pa, vh4[1], vh4[3]);
                }
            }
        }
        __syncthreads();   // stage reads done before refill
    }

    // ---- normalize + write y [B,T,C] as fp16 (feeds fp16 proj GEMM) ----
    const int g  = lane >> 2;
    const int t2 = (lane & 3) * 2;
    const int bb = bh >> 4, hh = bh & (NH - 1);
    const int row0 = qt*128 + (wid << 4) + g;
    const float inv0 = 1.0f / l0, inv1 = 1.0f / l1;
    uint32_t* y0 = (uint32_t*)(g_yf + ((size_t)bb*TT + row0)*CC + hh*DH);
    uint32_t* y1 = (uint32_t*)(g_yf + ((size_t)bb*TT + row0 + 8)*CC + hh*DH);
    #pragma unroll
    for (int nt = 0; nt < 8; nt++) {
        y0[(nt*8 + t2) >> 1] = pack_hf(oacc[nt][0]*inv0, oacc[nt][1]*inv0);
        y1[(nt*8 + t2) >> 1] = pack_hf(oacc[nt][2]*inv1, oacc[nt][3]*inv1);
    }
}

// ---------------------------------------------------------------------------
extern "C" void kernel_launch(void* const* d_in, const int* in_sizes, int n_in,
                              void* d_out, int out_size)
{
    (void)in_sizes; (void)n_in; (void)out_size;
    const float* x     = (const float*)d_in[0];
    const float* Wqkv  = (const float*)d_in[1];
    const float* bqkv  = (const float*)d_in[2];
    const float* Wproj = (const float*)d_in[3];
    const float* bproj = (const float*)d_in[4];
    float* out = (float*)d_out;

    static bool attr_set = false;
    if (!attr_set) {
        cudaFuncSetAttribute(flash_mma_kernel,
            cudaFuncAttributeMaxDynamicSharedMemorySize, FL_SMEM_BYTES);
        cudaFuncSetAttribute(gemm_f16_kernel<0>,
            cudaFuncAttributeMaxDynamicSharedMemorySize, GEMM_SMEM);
        cudaFuncSetAttribute(gemm_f16_kernel<1>,
            cudaFuncAttributeMaxDynamicSharedMemorySize, GEMM_SMEM);
        attr_set = true;
    }

    const int act4 = (MROWS * KDIM) / 4;

    // 0) conversions (all single fp16 planes)
    conv_x<<<act4 / 256, 256>>>(x);
    conv_w<3072><<<dim3(KDIM/32, 3072/32), dim3(32, 8)>>>(Wqkv);
    conv_w<1024><<<dim3(KDIM/32, 1024/32), dim3(32, 8)>>>(Wproj);

    // 1) QKV projection (single-term fp16) -> q,k,v fp16 [B,H,T,D]
    gemm_f16_kernel<0><<<dim3(3072/128, MROWS/128), 256, GEMM_SMEM>>>(bqkv, nullptr);

    // 2) causal flash attention (Br=128) -> g_yf fp16 [B,T,C]
    flash_mma_kernel<<<dim3(TT/128, NB*NH), 256, FL_SMEM_BYTES>>>();

    // 3) output projection (single-term fp16) -> d_out
    gemm_f16_kernel<1><<<dim3(1024/128, MROWS/128), 256, GEMM_SMEM>>>(bproj, out);
}

// round 16
// speedup vs baseline: 2.3377x; 1.0091x over previous
#include <cuda_runtime.h>
#include <cuda_bf16.h>
#include <cuda_fp16.h>
#include <math.h>
#include <stdint.h>

#define NB 4
#define NH 16
#define TT 2048
#define DH 64
#define CC 1024
#define MROWS (NB*TT)   // 8192
#define KDIM  1024

// ---------------------------------------------------------------------------
// Scratch (__device__ globals; allocation-free rule)
// ---------------------------------------------------------------------------
// q, k, v: single fp16 planes [B,H,T,D]
__device__ __half g_qf[NB*NH*TT*DH];
__device__ __half g_kf[NB*NH*TT*DH];
__device__ __half g_vf[NB*NH*TT*DH];

// y (attention out) single fp16 plane [B,T,C], written by flash epilogue
__device__ __half g_yf[(size_t)MROWS*KDIM];

// GEMM inputs: single fp16 planes
__device__ __half g_xf[(size_t)MROWS*KDIM];      // x
__device__ __half g_wqf[(size_t)3072*KDIM];      // Wqkv^T [3072][K]
__device__ __half g_wpf[(size_t)1024*KDIM];      // Wproj^T [1024][K]

// ---------------------------------------------------------------------------
// PTX helpers — compute_80-era ops only (harness PTX target lacks 'a' features)
// ---------------------------------------------------------------------------
__device__ __forceinline__ uint32_t smem_to_u32(const void* p) {
    uint32_t a;
    asm("{ .reg .u64 t; cvta.to.shared.u64 t, %1; cvt.u32.u64 %0, t; }"
        : "=r"(a) : "l"(p));
    return a;
}
__device__ __forceinline__ void cp16(uint32_t saddr, const void* g) {
    asm volatile("cp.async.cg.shared.global [%0], [%1], 16;"
                 :: "r"(saddr), "l"(g) : "memory");
}
__device__ __forceinline__ void ldm_x4(uint32_t (&r)[4], uint32_t addr) {
    asm volatile("ldmatrix.sync.aligned.m8n8.x4.shared.b16 {%0,%1,%2,%3}, [%4];"
        : "=r"(r[0]), "=r"(r[1]), "=r"(r[2]), "=r"(r[3]) : "r"(addr));
}
__device__ __forceinline__ void ldm_x4_t(uint32_t (&r)[4], uint32_t addr) {
    asm volatile("ldmatrix.sync.aligned.m8n8.x4.trans.shared.b16 {%0,%1,%2,%3}, [%4];"
        : "=r"(r[0]), "=r"(r[1]), "=r"(r[2]), "=r"(r[3]) : "r"(addr));
}
__device__ __forceinline__ void mma_f16(float (&d)[4], const uint32_t (&a)[4],
                                        uint32_t b0, uint32_t b1) {
    asm volatile("mma.sync.aligned.m16n8k16.row.col.f32.f16.f16.f32 "
        "{%0,%1,%2,%3}, {%4,%5,%6,%7}, {%8,%9}, {%0,%1,%2,%3};"
        : "+f"(d[0]), "+f"(d[1]), "+f"(d[2]), "+f"(d[3])
        : "r"(a[0]), "r"(a[1]), "r"(a[2]), "r"(a[3]), "r"(b0), "r"(b1));
}
// pack two fp32 into f16x2 word: low half = lo_elem
__device__ __forceinline__ uint32_t pack_hf(float lo_elem, float hi_elem) {
    __half2 h = __floats2half2_rn(lo_elem, hi_elem);
    return *(uint32_t*)&h;
}

// ---------------------------------------------------------------------------
// Conversion kernels
// ---------------------------------------------------------------------------
// x -> g_xf (single fp16 plane)
__global__ __launch_bounds__(256) void conv_x(const float* __restrict__ in)
{
    const size_t i = (size_t)blockIdx.x * 256 + threadIdx.x;   // per float4
    float4 v = ((const float4*)in)[i];
    __half h[4];
    h[0] = __float2half_rn(v.x); h[1] = __float2half_rn(v.y);
    h[2] = __float2half_rn(v.z); h[3] = __float2half_rn(v.w);
    *(uint2*)(g_xf + 4*i) = *(uint2*)h;
}

// W [K][N] -> out [N][K] (single fp16 plane, transposed)
template<int N>
__global__ __launch_bounds__(256) void conv_w(const float* __restrict__ W)
{
    __half* out = (N == 3072) ? g_wqf : g_wpf;
    __shared__ float t[32][33];
    const int k0 = blockIdx.x * 32, n0 = blockIdx.y * 32;
    const int tx = threadIdx.x, ty = threadIdx.y;      // 32 x 8
    #pragma unroll
    for (int i = 0; i < 4; i++)
        t[ty + 8*i][tx] = W[(size_t)(k0 + ty + 8*i) * N + n0 + tx];
    __syncthreads();
    #pragma unroll
    for (int i = 0; i < 4; i++)
        out[(size_t)(n0 + ty + 8*i) * KDIM + k0 + tx] =
            __float2half_rn(t[tx][ty + 8*i]);
}

#define PLANE_BYTES 10240          // 128 rows * 80 B (32 elems*2B + 16B pad)
#define GEMM_STAGE (2*PLANE_BYTES) // 20480
#define GEMM_SMEM  (4*GEMM_STAGE)  // 81920 (4-stage ring)

// ---------------------------------------------------------------------------
// Single-term fp16 GEMM core:  C[128x128 tile] = A @ B^T (+bias in epilogue)
// 256 threads, 8 warps, warp tile 32x64, 4-stage cp.async ring, BK=32,
// ONE __syncthreads per chunk (stage reuse guarded by the iteration barrier).
// MODE 0: A=g_xf, B=g_wqf (N=3072) -> q,k,v fp16 [B,H,T,D]
// MODE 1: A=g_yf, B=g_wpf (N=1024) -> Out fp32 [B,T,C]
// ---------------------------------------------------------------------------
template<int MODE>
__global__ __launch_bounds__(256, 2)
void gemm_f16_kernel(const float* __restrict__ bias, float* __restrict__ Out)
{
    extern __shared__ __align__(128) char smem[];
    const __half* __restrict__ Ap = MODE ? g_yf : g_xf;
    const __half* __restrict__ Bp = MODE ? g_wpf : g_wqf;

    const int tid  = threadIdx.x;
    const int lane = tid & 31, wid = tid >> 5;
    const int row0 = blockIdx.y * 128, col0 = blockIdx.x * 128;
    const int m0w  = (wid >> 1) * 32;
    const int n0w  = (wid & 1) * 64;
    const uint32_t sb = smem_to_u32(smem);

    float acc[2][8][4];
    #pragma unroll
    for (int a = 0; a < 2; a++)
        #pragma unroll
        for (int b = 0; b < 8; b++)
            #pragma unroll
            for (int c = 0; c < 4; c++) acc[a][b][c] = 0.f;

    auto issue = [&](int ck) {
        const int k0 = ck * 32;
        const uint32_t s0 = sb + (ck & 3) * GEMM_STAGE;
        #pragma unroll
        for (int i = 0; i < 2; i++) {
            const int c = tid + i * 256;       // 512 16B chunks per plane
            const int r = c >> 2, kc = c & 3;
            const uint32_t so = r * 80 + kc * 16;
            cp16(s0 + so, Ap + (size_t)(row0 + r) * KDIM + k0 + kc * 8);
            cp16(s0 + PLANE_BYTES + so,
                 Bp + (size_t)(col0 + r) * KDIM + k0 + kc * 8);
        }
        asm volatile("cp.async.commit_group;" ::: "memory");
    };

    auto compute = [&](int st) {
        const uint32_t s0 = sb + st * GEMM_STAGE;
        const uint32_t rsel = (lane & 15);
        #pragma unroll
        for (int ks = 0; ks < 32; ks += 16) {
            const uint32_t coff = ks * 2 + 16 * (lane >> 4);
            uint32_t af[2][4];
            #pragma unroll
            for (int mt = 0; mt < 2; mt++)
                ldm_x4(af[mt], s0 + (m0w + mt*16 + rsel) * 80 + coff);
            #pragma unroll
            for (int nt = 0; nt < 4; nt++) {
                uint32_t bh[4];
                ldm_x4(bh, s0 + PLANE_BYTES + (n0w + nt*16 + rsel) * 80 + coff);
                #pragma unroll
                for (int mt = 0; mt < 2; mt++) {
                    mma_f16(acc[mt][nt*2],   af[mt], bh[0], bh[2]);
                    mma_f16(acc[mt][nt*2+1], af[mt], bh[1], bh[3]);
                }
            }
        }
    };

    issue(0); issue(1); issue(2);
    for (int ck = 0; ck < 32; ck++) {
        if (ck < 30)      { asm volatile("cp.async.wait_group 2;" ::: "memory"); }
        else if (ck == 30){ asm volatile("cp.async.wait_group 1;" ::: "memory"); }
        else              { asm volatile("cp.async.wait_group 0;" ::: "memory"); }
        __syncthreads();   // all warps done with stage (ck-1)&3 -> safe to refill
        if (ck + 3 < 32) issue(ck + 3);
        compute(ck & 3);
    }

    // ---- epilogue ----
    const int g   = lane >> 2;
    const int cql = (lane & 3) * 2;
    #pragma unroll
    for (int mt = 0; mt < 2; mt++) {
        #pragma unroll
        for (int nt = 0; nt < 8; nt++) {
            const int cg = col0 + n0w + nt * 8 + cql;
            const float b0 = bias[cg], b1 = bias[cg + 1];
            const int r0 = row0 + m0w + mt * 16 + g;
            if (MODE == 0) {
                const int which = cg >> 10;
                const int rem = cg & (CC - 1);
                const int h = rem >> 6, d0 = rem & (DH - 1);
                uint32_t* dst = (which == 0) ? (uint32_t*)g_qf
                              : (which == 1) ? (uint32_t*)g_kf
                                             : (uint32_t*)g_vf;
                #pragma unroll
                for (int hf = 0; hf < 2; hf++) {
                    const float vx = acc[mt][nt][hf*2]   + b0;
                    const float vy = acc[mt][nt][hf*2+1] + b1;
                    const int rr = r0 + hf * 8;
                    const int bb = rr >> 11, t = rr & (TT - 1);
                    const size_t off = (((size_t)(bb*NH + h)*TT + t)*DH + d0) >> 1;
                    dst[off] = pack_hf(vx, vy);
                }
            } else {
                *(float2*)(Out + (size_t)r0 * CC + cg) =
                    make_float2(acc[mt][nt][0] + b0, acc[mt][nt][1] + b1);
                *(float2*)(Out + (size_t)(r0 + 8) * CC + cg) =
                    make_float2(acc[mt][nt][2] + b0, acc[mt][nt][3] + b1);
            }
        }
    }
}

// ---------------------------------------------------------------------------
// Flash attention on mma.sync, single fp16 planes.
// Br=128 (8 warps x m16), Bc=64. 3-stage cp.async ring, ONE sync per KV tile.
// Per-warp early-out on fully-masked diagonal sub-tiles.
// Epilogue writes y directly as fp16 (g_yf) for the fp16 proj GEMM.
// ---------------------------------------------------------------------------
#define QPL  9216                    // 64 * 144   (KV plane)
#define QPL2 18432                   // 128 * 144  (Q plane)
#define FL_STAGE (2*QPL)             // K, V
#define FL_SMEM_BYTES (QPL2 + 3*FL_STAGE)   // 73728 (3-stage ring)

__global__ __launch_bounds__(256)
void flash_mma_kernel()
{
    extern __shared__ __align__(128) char smem[];
    const uint32_t sb = smem_to_u32(smem);
    const int tid = threadIdx.x, lane = tid & 31, wid = tid >> 5;
    const int qt = (int)gridDim.x - 1 - (int)blockIdx.x;   // heavy tiles first
    const int bh = blockIdx.y;
    const size_t base = (size_t)bh * TT * DH;
    const int jmax = 2*qt + 1;

    // Q plane (128 rows) -> smem, part of cp.async group 0
    {
        const __half* q0 = g_qf + base + (size_t)qt * 128 * DH;
        #pragma unroll
        for (int i = 0; i < 4; i++) {
            const int ch = tid + i * 256;        // 1024 chunks
            const int r = ch >> 3, c = ch & 7;
            cp16(sb + r*144 + c*16, q0 + r*DH + c*8);
        }
    }
    const __half* kh = g_kf + base;
    const __half* vh = g_vf + base;

    auto issue_kv = [&](int jc, int st) {
        const uint32_t d0 = sb + QPL2 + st*FL_STAGE;
        const size_t g0 = (size_t)jc * 64 * DH;
        #pragma unroll
        for (int i = 0; i < 2; i++) {
            const int ch = tid + i * 256;        // 512 chunks per plane
            const int r = ch >> 3, c = ch & 7;
            const uint32_t so = r*144 + c*16;
            const size_t go = g0 + (size_t)r*DH + c*8;
            cp16(d0 +       so, kh + go);
            cp16(d0 + QPL + so, vh + go);
        }
        asm volatile("cp.async.commit_group;" ::: "memory");
    };

    issue_kv(0, 0);   // group 0 (includes Q)
    issue_kv(1, 1);   // jmax >= 1 always

    uint32_t qf[4][4];
    float oacc[8][4];
    #pragma unroll
    for (int nt = 0; nt < 8; nt++)
        #pragma unroll
        for (int e = 0; e < 4; e++) oacc[nt][e] = 0.f;
    float m0 = -INFINITY, m1 = -INFINITY, l0 = 0.f, l1 = 0.f;

    const int rsel = lane & 15;
    const uint32_t chalf = 16 * (lane >> 4);
    const int vrow = (lane & 7) + 8 * ((lane >> 4) & 1);
    const uint32_t vcol = 16 * ((lane >> 3) & 1);
    const int wrow_max = qt*128 + wid*16 + 15;   // warp's max global q-row

    int st = 0, stn = 2;    // current compute stage, next issue stage (mod 3)
    for (int jc = 0; jc <= jmax; jc++) {
        if (jc < jmax) { asm volatile("cp.async.wait_group 1;" ::: "memory"); }
        else           { asm volatile("cp.async.wait_group 0;" ::: "memory"); }
        __syncthreads();   // all warps done with stage (jc-1)%3 -> safe to refill
        if (jc + 2 <= jmax) issue_kv(jc + 2, stn);

        if (jc == 0) {   // Q fragments once (warp wid owns rows wid*16..+15)
            #pragma unroll
            for (int ku = 0; ku < 4; ku++)
                ldm_x4(qf[ku], sb + (uint32_t)((wid << 4) + rsel)*144 + ku*32 + chalf);
        }

        // fully-masked diagonal sub-tile for this warp -> skip body
        if (jc*64 <= wrow_max) {
            const uint32_t s0 = sb + QPL2 + st*FL_STAGE;

            // ---- S = Q @ K^T (single fp16) ----
            float s[8][4];
            #pragma unroll
            for (int nt = 0; nt < 8; nt++)
                #pragma unroll
                for (int e = 0; e < 4; e++) s[nt][e] = 0.f;

            #pragma unroll
            for (int ku = 0; ku < 4; ku++) {
                #pragma unroll
                for (int ng = 0; ng < 4; ng++) {
                    uint32_t kh4[4];
                    ldm_x4(kh4, s0 + (uint32_t)(ng*16 + rsel)*144 + ku*32 + chalf);
                    mma_f16(s[ng*2],   qf[ku], kh4[0], kh4[2]);
                    mma_f16(s[ng*2+1], qf[ku], kh4[1], kh4[3]);
                }
            }

            // ---- scale + causal mask (last two KV tiles only) ----
            #pragma unroll
            for (int nt = 0; nt < 8; nt++)
                #pragma unroll
                for (int e = 0; e < 4; e++) s[nt][e] *= 0.125f;
            if (jc >= 2*qt) {
                const int r0l = qt*128 + wid*16 + (lane >> 2);
                const int cbb = jc*64 + (lane & 3) * 2;
                #pragma unroll
                for (int nt = 0; nt < 8; nt++) {
                    const int c0 = cbb + nt*8;
                    if (c0     > r0l    ) s[nt][0] = -INFINITY;
                    if (c0 + 1 > r0l    ) s[nt][1] = -INFINITY;
                    if (c0     > r0l + 8) s[nt][2] = -INFINITY;
                    if (c0 + 1 > r0l + 8) s[nt][3] = -INFINITY;
                }
            }

            // ---- online softmax (rows g and g+8; row on 4 lanes) ----
            float mx0 = -INFINITY, mx1 = -INFINITY;
            #pragma unroll
            for (int nt = 0; nt < 8; nt++) {
                mx0 = fmaxf(mx0, fmaxf(s[nt][0], s[nt][1]));
                mx1 = fmaxf(mx1, fmaxf(s[nt][2], s[nt][3]));
            }
            mx0 = fmaxf(mx0, __shfl_xor_sync(0xffffffffu, mx0, 1));
            mx0 = fmaxf(mx0, __shfl_xor_sync(0xffffffffu, mx0, 2));
            mx1 = fmaxf(mx1, __shfl_xor_sync(0xffffffffu, mx1, 1));
            mx1 = fmaxf(mx1, __shfl_xor_sync(0xffffffffu, mx1, 2));
            const float mn0 = fmaxf(m0, mx0), mn1 = fmaxf(m1, mx1);
            const float a0 = __expf(m0 - mn0), a1 = __expf(m1 - mn1);
            float sum0 = 0.f, sum1 = 0.f;
            #pragma unroll
            for (int nt = 0; nt < 8; nt++) {
                s[nt][0] = __expf(s[nt][0] - mn0); sum0 += s[nt][0];
                s[nt][1] = __expf(s[nt][1] - mn0); sum0 += s[nt][1];
                s[nt][2] = __expf(s[nt][2] - mn1); sum1 += s[nt][2];
                s[nt][3] = __expf(s[nt][3] - mn1); sum1 += s[nt][3];
            }
            sum0 += __shfl_xor_sync(0xffffffffu, sum0, 1);
            sum0 += __shfl_xor_sync(0xffffffffu, sum0, 2);
            sum1 += __shfl_xor_sync(0xffffffffu, sum1, 1);
            sum1 += __shfl_xor_sync(0xffffffffu, sum1, 2);
            l0 = l0 * a0 + sum0;  m0 = mn0;
            l1 = l1 * a1 + sum1;  m1 = mn1;
            #pragma unroll
            for (int nt = 0; nt < 8; nt++) {
                oacc[nt][0] *= a0; oacc[nt][1] *= a0;
                oacc[nt][2] *= a1; oacc[nt][3] *= a1;
            }

            // ---- O += P @ V (fp16 P, single fp16 V) ----
            #pragma unroll
            for (int u = 0; u < 4; u++) {
                uint32_t pa[4];
                #pragma unroll
                for (int t = 0; t < 4; t++) {
                    const int j = 2*u + (t >> 1);
                    const int e0 = (t & 1) * 2;
                    pa[t] = pack_hf(s[j][e0], s[j][e0 + 1]);
                }
                #pragma unroll
                for (int dg = 0; dg < 4; dg++) {
                    uint32_t vh4[4];
                    ldm_x4_t(vh4, s0 + QPL + (uint32_t)(u*16 + vrow)*144 + dg*32 + vcol);
                    mma_f16(oacc[dg*2],   pa, vh4[0], vh4[2]);
                    mma_f16(oacc[dg*2+1], pa, vh4[1], vh4[3]);
                }
            }
        }
        st  = (st  == 2) ? 0 : st  + 1;
        stn = (stn == 2) ? 0 : stn + 1;
    }

    // ---- normalize + write y [B,T,C] as fp16 (feeds fp16 proj GEMM) ----
    const int g  = lane >> 2;
    const int t2 = (lane & 3) * 2;
    const int bb = bh >> 4, hh = bh & (NH - 1);
    const int row0 = qt*128 + (wid << 4) + g;
    const float inv0 = 1.0f / l0, inv1 = 1.0f / l1;
    uint32_t* y0 = (uint32_t*)(g_yf + ((size_t)bb*TT + row0)*CC + hh*DH);
    uint32_t* y1 = (uint32_t*)(g_yf + ((size_t)bb*TT + row0 + 8)*CC + hh*DH);
    #pragma unroll
    for (int nt = 0; nt < 8; nt++) {
        y0[(nt*8 + t2) >> 1] = pack_hf(oacc[nt][0]*inv0, oacc[nt][1]*inv0);
        y1[(nt*8 + t2) >> 1] = pack_hf(oacc[nt][2]*inv1, oacc[nt][3]*inv1);
    }
}

// ---------------------------------------------------------------------------
extern "C" void kernel_launch(void* const* d_in, const int* in_sizes, int n_in,
                              void* d_out, int out_size)
{
    (void)in_sizes; (void)n_in; (void)out_size;
    const float* x     = (const float*)d_in[0];
    const float* Wqkv  = (const float*)d_in[1];
    const float* bqkv  = (const float*)d_in[2];
    const float* Wproj = (const float*)d_in[3];
    const float* bproj = (const float*)d_in[4];
    float* out = (float*)d_out;

    static bool attr_set = false;
    if (!attr_set) {
        cudaFuncSetAttribute(flash_mma_kernel,
            cudaFuncAttributeMaxDynamicSharedMemorySize, FL_SMEM_BYTES);
        cudaFuncSetAttribute(gemm_f16_kernel<0>,
            cudaFuncAttributeMaxDynamicSharedMemorySize, GEMM_SMEM);
        cudaFuncSetAttribute(gemm_f16_kernel<1>,
            cudaFuncAttributeMaxDynamicSharedMemorySize, GEMM_SMEM);
        attr_set = true;
    }

    const int act4 = (MROWS * KDIM) / 4;

    // 0) conversions (all single fp16 planes)
    conv_x<<<act4 / 256, 256>>>(x);
    conv_w<3072><<<dim3(KDIM/32, 3072/32), dim3(32, 8)>>>(Wqkv);
    conv_w<1024><<<dim3(KDIM/32, 1024/32), dim3(32, 8)>>>(Wproj);

    // 1) QKV projection (single-term fp16) -> q,k,v fp16 [B,H,T,D]
    gemm_f16_kernel<0><<<dim3(3072/128, MROWS/128), 256, GEMM_SMEM>>>(bqkv, nullptr);

    // 2) causal flash attention (Br=128) -> g_yf fp16 [B,T,C]
    flash_mma_kernel<<<dim3(TT/128, NB*NH), 256, FL_SMEM_BYTES>>>();

    // 3) output projection (single-term fp16) -> d_out
    gemm_f16_kernel<1><<<dim3(1024/128, MROWS/128), 256, GEMM_SMEM>>>(bproj, out);
}